// round 3
// baseline (speedup 1.0000x reference)
#include <cuda_runtime.h>
#include <math.h>

#define BSZ 8192
#define DIM 2048
#define HID 512
#define NASP 3
#define EPSV 1e-5f

// ---------------- scratch (device globals; no allocation allowed) ----------------
__device__ float g_cat[(size_t)BSZ * 2 * DIM];   // concat input; reused as FFN hidden [B,4096]
__device__ float g_h1[(size_t)BSZ * HID];
__device__ float g_h2[(size_t)BSZ * (HID / 2)];
__device__ float g_gf[(size_t)BSZ * DIM];        // gate logits -> gated fusion
__device__ float g_q [(size_t)BSZ * DIM];
__device__ float g_k1[(size_t)BSZ * DIM];
__device__ float g_k2[(size_t)BSZ * DIM];
__device__ float g_v1[(size_t)BSZ * DIM];
__device__ float g_v2[(size_t)BSZ * DIM];
__device__ float g_r1[(size_t)BSZ * DIM];        // res1 -> normalized (in place)
__device__ float g_ffn[(size_t)BSZ * DIM];
__device__ float g_sum[NASP * DIM];
__device__ float g_sq [NASP * DIM];
__device__ float g_scale[NASP * DIM];
__device__ float g_shift[NASP * DIM];
__device__ float g_cnt[NASP];

__device__ __forceinline__ float gelu_exact(float x) {
    return 0.5f * x * (1.0f + erff(x * 0.7071067811865476f));
}

// Two-value block reduction for blockDim.x == 256.
__device__ __forceinline__ void blockReduce2(float& a, float& b) {
    __shared__ float sb[16];
    #pragma unroll
    for (int o = 16; o > 0; o >>= 1) {
        a += __shfl_down_sync(0xffffffffu, a, o);
        b += __shfl_down_sync(0xffffffffu, b, o);
    }
    int lane = threadIdx.x & 31, w = threadIdx.x >> 5;
    __syncthreads();                       // protect sb reuse across calls
    if (lane == 0) { sb[w] = a; sb[8 + w] = b; }
    __syncthreads();
    if (w == 0) {
        a = (lane < 8) ? sb[lane] : 0.0f;
        b = (lane < 8) ? sb[8 + lane] : 0.0f;
        #pragma unroll
        for (int o = 4; o > 0; o >>= 1) {
            a += __shfl_down_sync(0xffffffffu, a, o);
            b += __shfl_down_sync(0xffffffffu, b, o);
        }
        if (lane == 0) { sb[0] = a; sb[8] = b; }
    }
    __syncthreads();
    a = sb[0]; b = sb[8];
}

// ---------------- GEMM: C[M,N] = A[M,K] @ W[K,N] + bias, optional GELU -----------
// 128x128 tile, BK=16, 256 threads, 8x8 per-thread register tile.
// Requires M%128==0, N%128==0, K%16==0 (true for all shapes here).
__global__ __launch_bounds__(256) void gemm_k(
    const float* __restrict__ A, const float* __restrict__ W,
    const float* __restrict__ bias, float* __restrict__ C,
    int M, int N, int K, int epi /*0=none,1=gelu*/)
{
    __shared__ float As[16][128];
    __shared__ float Bs[16][128];
    const int tid = threadIdx.x;
    const int tx = tid & 15, ty = tid >> 4;
    const int mBase = blockIdx.y * 128;
    const int nBase = blockIdx.x * 128;

    float acc[8][8];
    #pragma unroll
    for (int i = 0; i < 8; i++)
        #pragma unroll
        for (int j = 0; j < 8; j++) acc[i][j] = 0.0f;

    for (int kt = 0; kt < K; kt += 16) {
        #pragma unroll
        for (int it = 0; it < 2; it++) {
            int f  = tid + it * 256;                 // 0..511
            int ar = f >> 2, kc = (f & 3) << 2;      // A: 4 float4 per row of 16
            float4 va = *(const float4*)(A + (size_t)(mBase + ar) * K + kt + kc);
            As[kc + 0][ar] = va.x; As[kc + 1][ar] = va.y;
            As[kc + 2][ar] = va.z; As[kc + 3][ar] = va.w;
            int kr = f >> 5, nc = (f & 31) << 2;     // W: 32 float4 per row of 128
            *(float4*)(&Bs[kr][nc]) =
                *(const float4*)(W + (size_t)(kt + kr) * N + nBase + nc);
        }
        __syncthreads();
        #pragma unroll
        for (int k = 0; k < 16; k++) {
            float4 a0 = *(float4*)&As[k][ty << 2];
            float4 a1 = *(float4*)&As[k][64 + (ty << 2)];
            float4 b0 = *(float4*)&Bs[k][tx << 2];
            float4 b1 = *(float4*)&Bs[k][64 + (tx << 2)];
            float av[8] = {a0.x, a0.y, a0.z, a0.w, a1.x, a1.y, a1.z, a1.w};
            float bv[8] = {b0.x, b0.y, b0.z, b0.w, b1.x, b1.y, b1.z, b1.w};
            #pragma unroll
            for (int i = 0; i < 8; i++)
                #pragma unroll
                for (int j = 0; j < 8; j++)
                    acc[i][j] = fmaf(av[i], bv[j], acc[i][j]);
        }
        __syncthreads();
    }

    float bv[8];
    #pragma unroll
    for (int j = 0; j < 8; j++) {
        int c = nBase + ((j < 4) ? (tx * 4 + j) : (64 + tx * 4 + (j - 4)));
        bv[j] = bias[c];
    }
    #pragma unroll
    for (int i = 0; i < 8; i++) {
        int r = mBase + ((i < 4) ? (ty * 4 + i) : (64 + ty * 4 + (i - 4)));
        float o[8];
        #pragma unroll
        for (int j = 0; j < 8; j++) {
            float v = acc[i][j] + bv[j];
            o[j] = (epi == 1) ? gelu_exact(v) : v;
        }
        float4 o0 = make_float4(o[0], o[1], o[2], o[3]);
        float4 o1 = make_float4(o[4], o[5], o[6], o[7]);
        *(float4*)(C + (size_t)r * N + nBase + tx * 4)      = o0;
        *(float4*)(C + (size_t)r * N + nBase + 64 + tx * 4) = o1;
    }
}

// ---------------- elementwise / rowwise kernels ----------------------------------

__global__ void concat_k(const float* __restrict__ f1, const float* __restrict__ f2) {
    int row = blockIdx.y;
    int col = blockIdx.x * 256 + threadIdx.x;       // grid.x = 4096/256 = 16
    float v = (col < DIM) ? f1[(size_t)row * DIM + col]
                          : f2[(size_t)row * DIM + (col - DIM)];
    g_cat[(size_t)row * (2 * DIM) + col] = v;
}

// In-place LayerNorm over last dim N, then optional exact GELU. One block per row.
__global__ __launch_bounds__(256) void ln_act_k(
    float* __restrict__ X, const float* __restrict__ g,
    const float* __restrict__ b, int N, int act)
{
    float* x = X + (size_t)blockIdx.x * N;
    float s = 0.0f, q = 0.0f;
    for (int i = threadIdx.x; i < N; i += 256) { float t = x[i]; s += t; q += t * t; }
    blockReduce2(s, q);
    float mu = s / N;
    float rstd = rsqrtf(q / N - mu * mu + EPSV);
    for (int i = threadIdx.x; i < N; i += 256) {
        float t = (x[i] - mu) * rstd * g[i] + b[i];
        if (act) t = gelu_exact(t);
        x[i] = t;
    }
}

__global__ void gate_k(const float* __restrict__ f1, const float* __restrict__ f2) {
    size_t i = (size_t)blockIdx.x * 256 + threadIdx.x;
    float gv = 1.0f / (1.0f + expf(-g_gf[i]));
    g_gf[i] = gv * f1[i] + (1.0f - gv) * f2[i];
}

// scores -> softmax(2) -> attn -> LN(gf+attn) -> LN(gated+f1) -> g_r1. Block per row.
__global__ __launch_bounds__(256) void attn_k(
    const float* __restrict__ f1,
    const float* __restrict__ alng, const float* __restrict__ alnb,
    const float* __restrict__ ln1g, const float* __restrict__ ln1b)
{
    size_t base = (size_t)blockIdx.x * DIM;
    int tid = threadIdx.x;
    float s1 = 0.0f, s2 = 0.0f;
    #pragma unroll
    for (int j = 0; j < 8; j++) {
        int c = tid + j * 256;
        float qq = g_q[base + c];
        s1 += qq * g_k1[base + c];
        s2 += qq * g_k2[base + c];
    }
    blockReduce2(s1, s2);
    const float inv = rsqrtf((float)DIM);
    float w1 = 1.0f / (1.0f + expf((s2 - s1) * inv));
    float w2 = 1.0f - w1;

    float t[8]; float s = 0.0f, q = 0.0f;
    #pragma unroll
    for (int j = 0; j < 8; j++) {
        int c = tid + j * 256;
        float tv = g_gf[base + c] + w1 * g_v1[base + c] + w2 * g_v2[base + c];
        t[j] = tv; s += tv; q += tv * tv;
    }
    blockReduce2(s, q);
    float mu = s / DIM, rstd = rsqrtf(q / DIM - mu * mu + EPSV);

    float r[8]; s = 0.0f; q = 0.0f;
    #pragma unroll
    for (int j = 0; j < 8; j++) {
        int c = tid + j * 256;
        float gv = (t[j] - mu) * rstd * alng[c] + alnb[c];
        float rv = gv + f1[base + c];
        r[j] = rv; s += rv; q += rv * rv;
    }
    blockReduce2(s, q);
    mu = s / DIM; rstd = rsqrtf(q / DIM - mu * mu + EPSV);
    #pragma unroll
    for (int j = 0; j < 8; j++) {
        int c = tid + j * 256;
        g_r1[base + c] = (r[j] - mu) * rstd * ln1g[c] + ln1b[c];
    }
}

__global__ void zero_k() {
    int i = blockIdx.x * 256 + threadIdx.x;
    if (i < NASP * DIM) { g_sum[i] = 0.0f; g_sq[i] = 0.0f; }
    if (i < NASP) g_cnt[i] = 0.0f;
}

__global__ void cnt_k(const int* __restrict__ asp) {
    __shared__ int c[NASP];
    if (threadIdx.x < NASP) c[threadIdx.x] = 0;
    __syncthreads();
    for (int i = threadIdx.x; i < BSZ; i += blockDim.x) atomicAdd(&c[asp[i]], 1);
    __syncthreads();
    if (threadIdx.x < NASP) g_cnt[threadIdx.x] = (float)c[threadIdx.x];
}

// Per-aspect column sums / sumsq. grid (DIM/128, BSZ/128), 128 threads.
__global__ __launch_bounds__(128) void bnstat_k(const int* __restrict__ asp) {
    int col = blockIdx.x * 128 + threadIdx.x;
    int r0 = blockIdx.y * 128;
    float m0 = 0, m1 = 0, m2 = 0, q0 = 0, q1 = 0, q2 = 0;
    for (int r = r0; r < r0 + 128; r++) {
        int a = asp[r];
        float x = g_r1[(size_t)r * DIM + col];
        float xx = x * x;
        if (a == 0)      { m0 += x; q0 += xx; }
        else if (a == 1) { m1 += x; q1 += xx; }
        else             { m2 += x; q2 += xx; }
    }
    atomicAdd(&g_sum[0 * DIM + col], m0); atomicAdd(&g_sq[0 * DIM + col], q0);
    atomicAdd(&g_sum[1 * DIM + col], m1); atomicAdd(&g_sq[1 * DIM + col], q1);
    atomicAdd(&g_sum[2 * DIM + col], m2); atomicAdd(&g_sq[2 * DIM + col], q2);
}

__global__ void bnfin_k(const float* __restrict__ bng, const float* __restrict__ bnb) {
    int i = blockIdx.x * 256 + threadIdx.x;
    if (i >= NASP * DIM) return;
    int a = i / DIM;
    float safe = fmaxf(g_cnt[a], 1.0f);
    float mean = g_sum[i] / safe;
    float var  = g_sq[i] / safe - mean * mean;     // biased, as in reference
    float sc = rsqrtf(var + EPSV) * bng[i];
    g_scale[i] = sc;
    g_shift[i] = bnb[i] - mean * sc;
}

__global__ __launch_bounds__(256) void bnapply_k(const int* __restrict__ asp) {
    int row = blockIdx.x;
    int a = asp[row];
    bool norm = g_cnt[a] > 1.0f;                   // passthrough when cnt<=1
    size_t base = (size_t)row * DIM;
    for (int c = threadIdx.x; c < DIM; c += 256) {
        float x = g_r1[base + c];
        g_r1[base + c] = norm ? fmaf(x, g_scale[a * DIM + c], g_shift[a * DIM + c]) : x;
    }
}

// out = LN(ffn + normalized). Block per row.
__global__ __launch_bounds__(256) void final_k(
    float* __restrict__ out,
    const float* __restrict__ ln2g, const float* __restrict__ ln2b)
{
    size_t base = (size_t)blockIdx.x * DIM;
    int tid = threadIdx.x;
    float t[8]; float s = 0.0f, q = 0.0f;
    #pragma unroll
    for (int j = 0; j < 8; j++) {
        int c = tid + j * 256;
        float tv = g_ffn[base + c] + g_r1[base + c];
        t[j] = tv; s += tv; q += tv * tv;
    }
    blockReduce2(s, q);
    float mu = s / DIM, rstd = rsqrtf(q / DIM - mu * mu + EPSV);
    #pragma unroll
    for (int j = 0; j < 8; j++) {
        int c = tid + j * 256;
        out[base + c] = (t[j] - mu) * rstd * ln2g[c] + ln2b[c];
    }
}

// ---------------- launch -----------------------------------------------------
static inline dim3 gemm_grid(int M, int N) { return dim3(N / 128, M / 128); }

extern "C" void kernel_launch(void* const* d_in, const int* in_sizes, int n_in,
                              void* d_out, int out_size)
{
    (void)in_sizes; (void)n_in; (void)out_size;
    const float* f1   = (const float*)d_in[0];
    const float* f2   = (const float*)d_in[1];
    const int*   asp  = (const int*)  d_in[2];
    const float* gW1  = (const float*)d_in[3];
    const float* gb1  = (const float*)d_in[4];
    const float* gl1g = (const float*)d_in[5];
    const float* gl1b = (const float*)d_in[6];
    const float* gW2  = (const float*)d_in[7];
    const float* gb2  = (const float*)d_in[8];
    const float* gl2g = (const float*)d_in[9];
    const float* gl2b = (const float*)d_in[10];
    const float* gW3  = (const float*)d_in[11];
    const float* gb3  = (const float*)d_in[12];
    const float* qW   = (const float*)d_in[13];
    const float* qb   = (const float*)d_in[14];
    const float* kW   = (const float*)d_in[15];
    const float* kb   = (const float*)d_in[16];
    const float* vW   = (const float*)d_in[17];
    const float* vb   = (const float*)d_in[18];
    const float* alng = (const float*)d_in[19];
    const float* alnb = (const float*)d_in[20];
    const float* bng  = (const float*)d_in[21];
    const float* bnb  = (const float*)d_in[22];
    const float* ln1g = (const float*)d_in[23];
    const float* ln1b = (const float*)d_in[24];
    const float* fW1  = (const float*)d_in[25];
    const float* fb1  = (const float*)d_in[26];
    const float* fW2  = (const float*)d_in[27];
    const float* fb2  = (const float*)d_in[28];
    const float* ln2g = (const float*)d_in[29];
    const float* ln2b = (const float*)d_in[30];
    float* out = (float*)d_out;

    float *p_cat, *p_h1, *p_h2, *p_gf, *p_q, *p_k1, *p_k2, *p_v1, *p_v2, *p_r1, *p_ffn;
    cudaGetSymbolAddress((void**)&p_cat, g_cat);
    cudaGetSymbolAddress((void**)&p_h1,  g_h1);
    cudaGetSymbolAddress((void**)&p_h2,  g_h2);
    cudaGetSymbolAddress((void**)&p_gf,  g_gf);
    cudaGetSymbolAddress((void**)&p_q,   g_q);
    cudaGetSymbolAddress((void**)&p_k1,  g_k1);
    cudaGetSymbolAddress((void**)&p_k2,  g_k2);
    cudaGetSymbolAddress((void**)&p_v1,  g_v1);
    cudaGetSymbolAddress((void**)&p_v2,  g_v2);
    cudaGetSymbolAddress((void**)&p_r1,  g_r1);
    cudaGetSymbolAddress((void**)&p_ffn, g_ffn);

    // 1) concat [f1|f2]
    concat_k<<<dim3(2 * DIM / 256, BSZ), 256>>>(f1, f2);
    // 2) gate MLP
    gemm_k<<<gemm_grid(BSZ, HID), 256>>>(p_cat, gW1, gb1, p_h1, BSZ, HID, 2 * DIM, 0);
    ln_act_k<<<BSZ, 256>>>(p_h1, gl1g, gl1b, HID, 1);
    gemm_k<<<gemm_grid(BSZ, HID / 2), 256>>>(p_h1, gW2, gb2, p_h2, BSZ, HID / 2, HID, 0);
    ln_act_k<<<BSZ, 256>>>(p_h2, gl2g, gl2b, HID / 2, 1);
    gemm_k<<<gemm_grid(BSZ, DIM), 256>>>(p_h2, gW3, gb3, p_gf, BSZ, DIM, HID / 2, 0);
    gate_k<<<(BSZ * DIM) / 256, 256>>>(f1, f2);
    // 3) attention projections
    gemm_k<<<gemm_grid(BSZ, DIM), 256>>>(p_gf, qW, qb, p_q,  BSZ, DIM, DIM, 0);
    gemm_k<<<gemm_grid(BSZ, DIM), 256>>>(f1,   kW, kb, p_k1, BSZ, DIM, DIM, 0);
    gemm_k<<<gemm_grid(BSZ, DIM), 256>>>(f2,   kW, kb, p_k2, BSZ, DIM, DIM, 0);
    gemm_k<<<gemm_grid(BSZ, DIM), 256>>>(f1,   vW, vb, p_v1, BSZ, DIM, DIM, 0);
    gemm_k<<<gemm_grid(BSZ, DIM), 256>>>(f2,   vW, vb, p_v2, BSZ, DIM, DIM, 0);
    // 4) attn combine + LN(gf+attn) + LN(gated+f1) -> g_r1
    attn_k<<<BSZ, 256>>>(f1, alng, alnb, ln1g, ln1b);
    // 5) aspect BN (train-mode batch stats)
    zero_k<<<(NASP * DIM + 255) / 256, 256>>>();
    cnt_k<<<1, 256>>>(asp);
    bnstat_k<<<dim3(DIM / 128, BSZ / 128), 128>>>(asp);
    bnfin_k<<<(NASP * DIM + 255) / 256, 256>>>(bng, bnb);
    bnapply_k<<<BSZ, 256>>>(asp);
    // 6) FFN (gelu fused into first GEMM epilogue)
    gemm_k<<<gemm_grid(BSZ, 2 * DIM), 256>>>(p_r1, fW1, fb1, p_cat, BSZ, 2 * DIM, DIM, 1);
    gemm_k<<<gemm_grid(BSZ, DIM), 256>>>(p_cat, fW2, fb2, p_ffn, BSZ, DIM, 2 * DIM, 0);
    // 7) final LN
    final_k<<<BSZ, 256>>>(out, ln2g, ln2b);
}

// round 7
// speedup vs baseline: 2.6794x; 2.6794x over previous
#include <cuda_runtime.h>
#include <cuda_bf16.h>
#include <math.h>
#include <stdint.h>

typedef __nv_bfloat16 bf16;

#define BSZ 8192
#define DIM 2048
#define HID 512
#define NASP 3
#define EPSV 1e-5f

// ---------------- GEMM tiling (mma.sync path, base ISA only) ----------------
#define BM 128
#define BN 128
#define BKC 32
#define ROWP 40                      // padded row stride (elems) -> 80B, conflict-free ldmatrix
#define ARR_BYTES (128 * ROWP * 2)   // 10240 B per tile array
#define STAGE_BYTES (4 * ARR_BYTES)  // Ah, Al, Bh, Bl
#define GEMM_SMEM_BYTES (2 * STAGE_BYTES)   // 81920

// ---------------- fp32 scratch ----------------
__device__ float g_h1[(size_t)BSZ * HID];
__device__ float g_h2[(size_t)BSZ * (HID / 2)];
__device__ float g_gf[(size_t)BSZ * DIM];
__device__ float g_q [(size_t)BSZ * DIM];
__device__ float g_k1[(size_t)BSZ * DIM];
__device__ float g_k2[(size_t)BSZ * DIM];
__device__ float g_v1[(size_t)BSZ * DIM];
__device__ float g_v2[(size_t)BSZ * DIM];
__device__ float g_r1[(size_t)BSZ * DIM];
__device__ float g_ffn[(size_t)BSZ * DIM];
__device__ float g_sum[NASP * DIM];
__device__ float g_sq [NASP * DIM];
__device__ float g_scale[NASP * DIM];
__device__ float g_shift[NASP * DIM];
__device__ float g_cnt[NASP];

// ---------------- bf16 split activations ----------------
__device__ bf16 g_cath[(size_t)BSZ * 2 * DIM];
__device__ bf16 g_catl[(size_t)BSZ * 2 * DIM];
__device__ bf16 g_h1h[(size_t)BSZ * HID];
__device__ bf16 g_h1l[(size_t)BSZ * HID];
__device__ bf16 g_h2h[(size_t)BSZ * (HID / 2)];
__device__ bf16 g_h2l[(size_t)BSZ * (HID / 2)];
__device__ bf16 g_gfh[(size_t)BSZ * DIM];
__device__ bf16 g_gfl[(size_t)BSZ * DIM];
__device__ bf16 g_f1h[(size_t)BSZ * DIM];
__device__ bf16 g_f1l[(size_t)BSZ * DIM];
__device__ bf16 g_f2h[(size_t)BSZ * DIM];
__device__ bf16 g_f2l[(size_t)BSZ * DIM];
__device__ bf16 g_r1h[(size_t)BSZ * DIM];
__device__ bf16 g_r1l[(size_t)BSZ * DIM];
__device__ bf16 g_hidh[(size_t)BSZ * 2 * DIM];
__device__ bf16 g_hidl[(size_t)BSZ * 2 * DIM];

// ---------------- bf16 transposed-split weights ([N,K] K-major) ----------------
__device__ bf16 w_g1h[(size_t)HID * 2 * DIM];       __device__ bf16 w_g1l[(size_t)HID * 2 * DIM];
__device__ bf16 w_g2h[(size_t)(HID/2) * HID];       __device__ bf16 w_g2l[(size_t)(HID/2) * HID];
__device__ bf16 w_g3h[(size_t)DIM * (HID/2)];       __device__ bf16 w_g3l[(size_t)DIM * (HID/2)];
__device__ bf16 w_qh [(size_t)DIM * DIM];           __device__ bf16 w_ql [(size_t)DIM * DIM];
__device__ bf16 w_kh [(size_t)DIM * DIM];           __device__ bf16 w_kl [(size_t)DIM * DIM];
__device__ bf16 w_vh [(size_t)DIM * DIM];           __device__ bf16 w_vl [(size_t)DIM * DIM];
__device__ bf16 w_f1h[(size_t)(2*DIM) * DIM];       __device__ bf16 w_f1l[(size_t)(2*DIM) * DIM];
__device__ bf16 w_f2h[(size_t)DIM * 2 * DIM];       __device__ bf16 w_f2l[(size_t)DIM * 2 * DIM];

// ============================ helpers ============================
__device__ __forceinline__ uint32_t smem_u32(const void* p) {
    uint32_t a;
    asm("{ .reg .u64 t; cvta.to.shared.u64 t, %1; cvt.u32.u64 %0, t; }" : "=r"(a) : "l"(p));
    return a;
}
__device__ __forceinline__ void cp16(uint32_t s, const void* g) {
    asm volatile("cp.async.cg.shared.global [%0], [%1], 16;" :: "r"(s), "l"(g));
}
__device__ __forceinline__ void cp_commit() { asm volatile("cp.async.commit_group;" ::: "memory"); }
__device__ __forceinline__ void cp_wait1()  { asm volatile("cp.async.wait_group 1;" ::: "memory"); }

__device__ __forceinline__ void ldsm4(uint32_t* r, uint32_t addr) {
    asm volatile("ldmatrix.sync.aligned.m8n8.x4.shared.b16 {%0,%1,%2,%3}, [%4];"
                 : "=r"(r[0]), "=r"(r[1]), "=r"(r[2]), "=r"(r[3]) : "r"(addr));
}
__device__ __forceinline__ void mma16816(float* c, const uint32_t* a, uint32_t b0, uint32_t b1) {
    asm volatile("mma.sync.aligned.m16n8k16.row.col.f32.bf16.bf16.f32 "
                 "{%0,%1,%2,%3}, {%4,%5,%6,%7}, {%8,%9}, {%0,%1,%2,%3};"
                 : "+f"(c[0]), "+f"(c[1]), "+f"(c[2]), "+f"(c[3])
                 : "r"(a[0]), "r"(a[1]), "r"(a[2]), "r"(a[3]), "r"(b0), "r"(b1));
}

__device__ __forceinline__ float gelu_exact(float x) {
    return 0.5f * x * (1.0f + erff(x * 0.7071067811865476f));
}
__device__ __forceinline__ void split1(float v, bf16& h, bf16& l) {
    h = __float2bfloat16_rn(v);
    l = __float2bfloat16_rn(v - __bfloat162float(h));
}

// ============================ split-bf16 mma.sync GEMM ============================
// C[M,N] = (Ah+Al)[M,K] @ (Bh+Bl)^T, B arrays [N,K] K-major (mma row.col).
// 3-product compensated fp32 accumulation in registers.
// epi: 0 = bias -> C fp32; 1 = bias+gelu -> C fp32; 2 = bias+gelu -> split bf16 Ch/Cl.
__global__ __launch_bounds__(256)
void gemm_mma_k(const bf16* __restrict__ Ah, const bf16* __restrict__ Al,
                const bf16* __restrict__ Bh, const bf16* __restrict__ Bl,
                const float* __restrict__ bias,
                float* __restrict__ C, bf16* __restrict__ Ch, bf16* __restrict__ Cl,
                int M, int N, int K, int epi)
{
    extern __shared__ char smem[];
    const uint32_t sb = smem_u32(smem);

    const int tid  = threadIdx.x;
    const int wid  = tid >> 5, lane = tid & 31;
    const int mBase = blockIdx.y * BM;
    const int nBase = blockIdx.x * BN;
    const int warp_m = wid >> 2;            // 0..1 -> 64-row slab
    const int warp_n = wid & 3;             // 0..3 -> 32-col slab

    // ldmatrix lane offsets (bytes within one tile array)
    const uint32_t aLM = (uint32_t)((warp_m * 64 + (lane & 15)) * (ROWP * 2) + ((lane >> 4) << 3) * 2);
    const uint32_t bLM = (uint32_t)((warp_n * 32 + ((lane >> 4) << 3) + (lane & 7)) * (ROWP * 2)
                                    + (((lane >> 3) & 1) << 3) * 2);

    float acc[4][4][4];
    #pragma unroll
    for (int i = 0; i < 4; i++)
        #pragma unroll
        for (int j = 0; j < 4; j++)
            #pragma unroll
            for (int v = 0; v < 4; v++) acc[i][j][v] = 0.0f;

    // cp.async fill of one stage: 2048 chunks of 16B; 8 per thread.
    // chunk u = tid + i*256 -> arr = i>>1, r = (tid>>2) + (i&1)*64, c = tid&3
    const int rL = (tid >> 2), cL = tid & 3;
    auto fill = [&](int stage, int kt) {
        const uint32_t stB = sb + (uint32_t)stage * STAGE_BYTES;
        #pragma unroll
        for (int i = 0; i < 8; i++) {
            const int arr = i >> 1;
            const int r = rL + (i & 1) * 64;
            const bf16* base = (arr == 0) ? Ah : (arr == 1) ? Al : (arr == 2) ? Bh : Bl;
            const int rowIdx = (arr < 2) ? (mBase + r) : (nBase + r);
            const bf16* g = base + (size_t)rowIdx * K + kt + cL * 8;
            cp16(stB + (uint32_t)arr * ARR_BYTES + (uint32_t)(r * (ROWP * 2) + cL * 16), g);
        }
    };

    const int niter = K / BKC;
    fill(0, 0); cp_commit();
    if (niter > 1) fill(1, BKC);
    cp_commit();

    for (int it = 0; it < niter; ++it) {
        cp_wait1();
        __syncthreads();
        const uint32_t stB = sb + (uint32_t)(it & 1) * STAGE_BYTES;
        #pragma unroll
        for (int ks = 0; ks < 2; ks++) {     // two k16 steps per BK=32
            const uint32_t ksB = (uint32_t)(ks * 32);   // 16 elems * 2B
            const uint32_t aH = stB + 0 * ARR_BYTES + aLM + ksB;
            const uint32_t aL = stB + 1 * ARR_BYTES + aLM + ksB;
            const uint32_t bH = stB + 2 * ARR_BYTES + bLM + ksB;
            const uint32_t bL = stB + 3 * ARR_BYTES + bLM + ksB;

            uint32_t aF[4][4], bFh[2][4], bFl[2][4];
            #pragma unroll
            for (int am = 0; am < 4; am++) ldsm4(aF[am], aH + (uint32_t)(am * 16 * ROWP * 2));
            #pragma unroll
            for (int bt = 0; bt < 2; bt++) ldsm4(bFh[bt], bH + (uint32_t)(bt * 16 * ROWP * 2));
            #pragma unroll
            for (int bt = 0; bt < 2; bt++) ldsm4(bFl[bt], bL + (uint32_t)(bt * 16 * ROWP * 2));

            // Ah * Bh
            #pragma unroll
            for (int am = 0; am < 4; am++)
                #pragma unroll
                for (int bt = 0; bt < 2; bt++) {
                    mma16816(acc[am][bt * 2 + 0], aF[am], bFh[bt][0], bFh[bt][1]);
                    mma16816(acc[am][bt * 2 + 1], aF[am], bFh[bt][2], bFh[bt][3]);
                }
            // Ah * Bl
            #pragma unroll
            for (int am = 0; am < 4; am++)
                #pragma unroll
                for (int bt = 0; bt < 2; bt++) {
                    mma16816(acc[am][bt * 2 + 0], aF[am], bFl[bt][0], bFl[bt][1]);
                    mma16816(acc[am][bt * 2 + 1], aF[am], bFl[bt][2], bFl[bt][3]);
                }
            // Al * Bh (reload A fragments from Al array)
            #pragma unroll
            for (int am = 0; am < 4; am++) ldsm4(aF[am], aL + (uint32_t)(am * 16 * ROWP * 2));
            #pragma unroll
            for (int am = 0; am < 4; am++)
                #pragma unroll
                for (int bt = 0; bt < 2; bt++) {
                    mma16816(acc[am][bt * 2 + 0], aF[am], bFh[bt][0], bFh[bt][1]);
                    mma16816(acc[am][bt * 2 + 1], aF[am], bFh[bt][2], bFh[bt][3]);
                }
        }
        __syncthreads();
        if (it + 2 < niter) fill(it & 1, (it + 2) * BKC);
        cp_commit();
    }

    // ---- epilogue ----
    const int rowQ = lane >> 2, colQ = (lane & 3) * 2;
    #pragma unroll
    for (int am = 0; am < 4; am++) {
        const int r0 = mBase + warp_m * 64 + am * 16 + rowQ;
        #pragma unroll
        for (int bn = 0; bn < 4; bn++) {
            const int c0 = nBase + warp_n * 32 + bn * 8 + colQ;
            const float b0 = __ldg(bias + c0), b1 = __ldg(bias + c0 + 1);
            float v0 = acc[am][bn][0] + b0, v1 = acc[am][bn][1] + b1;
            float v2 = acc[am][bn][2] + b0, v3 = acc[am][bn][3] + b1;
            if (epi >= 1) {
                v0 = gelu_exact(v0); v1 = gelu_exact(v1);
                v2 = gelu_exact(v2); v3 = gelu_exact(v3);
            }
            if (epi == 2) {
                bf16 h0,l0,h1,l1;
                split1(v0, h0, l0); split1(v1, h1, l1);
                __nv_bfloat162 hv, lv; hv.x = h0; hv.y = h1; lv.x = l0; lv.y = l1;
                *(__nv_bfloat162*)(Ch + (size_t)r0 * N + c0) = hv;
                *(__nv_bfloat162*)(Cl + (size_t)r0 * N + c0) = lv;
                split1(v2, h0, l0); split1(v3, h1, l1);
                hv.x = h0; hv.y = h1; lv.x = l0; lv.y = l1;
                *(__nv_bfloat162*)(Ch + (size_t)(r0 + 8) * N + c0) = hv;
                *(__nv_bfloat162*)(Cl + (size_t)(r0 + 8) * N + c0) = lv;
            } else {
                float2 o0 = make_float2(v0, v1), o1 = make_float2(v2, v3);
                *(float2*)(C + (size_t)r0 * N + c0)       = o0;
                *(float2*)(C + (size_t)(r0 + 8) * N + c0) = o1;
            }
        }
    }
}

// ============================ pre-pass kernels ============================

// W [K,N] fp32 -> Wt hi/lo [N,K] bf16. 32x32 tiles, block (32,8).
__global__ void splitT_k(const float* __restrict__ W, bf16* __restrict__ ht,
                         bf16* __restrict__ lt, int K, int N)
{
    __shared__ float t[32][33];
    const int n0 = blockIdx.x * 32, k0 = blockIdx.y * 32;
    const int tx = threadIdx.x, ty = threadIdx.y;
    #pragma unroll
    for (int i = 0; i < 4; i++)
        t[ty + i * 8][tx] = W[(size_t)(k0 + ty + i * 8) * N + n0 + tx];
    __syncthreads();
    #pragma unroll
    for (int i = 0; i < 4; i++) {
        const int n = ty + i * 8;
        float v = t[tx][n];
        bf16 h, l; split1(v, h, l);
        const size_t o = (size_t)(n0 + n) * K + k0 + tx;
        ht[o] = h; lt[o] = l;
    }
}

__global__ void split_pair_k(const float* __restrict__ x, bf16* __restrict__ h,
                             bf16* __restrict__ l)
{
    const size_t i4 = ((size_t)blockIdx.x * 256 + threadIdx.x) * 4;
    float4 v = *(const float4*)(x + i4);
    bf16 h0,l0,h1,l1,h2,l2,h3,l3;
    split1(v.x,h0,l0); split1(v.y,h1,l1); split1(v.z,h2,l2); split1(v.w,h3,l3);
    __nv_bfloat162 a,b,c,d;
    a.x=h0;a.y=h1; b.x=h2;b.y=h3; c.x=l0;c.y=l1; d.x=l2;d.y=l3;
    *(__nv_bfloat162*)(h + i4)     = a; *(__nv_bfloat162*)(h + i4 + 2) = b;
    *(__nv_bfloat162*)(l + i4)     = c; *(__nv_bfloat162*)(l + i4 + 2) = d;
}

__global__ void splitcat_k(const float* __restrict__ f1, const float* __restrict__ f2) {
    const int row = blockIdx.y;
    const int c4 = (blockIdx.x * 256 + threadIdx.x) * 4;
    const float* src = (c4 < DIM) ? (f1 + (size_t)row * DIM + c4)
                                  : (f2 + (size_t)row * DIM + (c4 - DIM));
    float4 v = *(const float4*)src;
    bf16 h0,l0,h1,l1,h2,l2,h3,l3;
    split1(v.x,h0,l0); split1(v.y,h1,l1); split1(v.z,h2,l2); split1(v.w,h3,l3);
    const size_t o = (size_t)row * (2 * DIM) + c4;
    __nv_bfloat162 a,b,c,d;
    a.x=h0;a.y=h1; b.x=h2;b.y=h3; c.x=l0;c.y=l1; d.x=l2;d.y=l3;
    *(__nv_bfloat162*)(g_cath + o)     = a; *(__nv_bfloat162*)(g_cath + o + 2) = b;
    *(__nv_bfloat162*)(g_catl + o)     = c; *(__nv_bfloat162*)(g_catl + o + 2) = d;
}

// ============================ elementwise / rowwise ============================

__device__ __forceinline__ void blockReduce2(float& a, float& b) {
    __shared__ float sb[16];
    #pragma unroll
    for (int o = 16; o > 0; o >>= 1) {
        a += __shfl_down_sync(0xffffffffu, a, o);
        b += __shfl_down_sync(0xffffffffu, b, o);
    }
    int lane = threadIdx.x & 31, w = threadIdx.x >> 5;
    __syncthreads();
    if (lane == 0) { sb[w] = a; sb[8 + w] = b; }
    __syncthreads();
    if (w == 0) {
        a = (lane < 8) ? sb[lane] : 0.0f;
        b = (lane < 8) ? sb[8 + lane] : 0.0f;
        #pragma unroll
        for (int o = 4; o > 0; o >>= 1) {
            a += __shfl_down_sync(0xffffffffu, a, o);
            b += __shfl_down_sync(0xffffffffu, b, o);
        }
        if (lane == 0) { sb[0] = a; sb[8] = b; }
    }
    __syncthreads();
    a = sb[0]; b = sb[8];
}

__global__ __launch_bounds__(256) void ln_gelu_split_k(
    const float* __restrict__ X, const float* __restrict__ g, const float* __restrict__ b,
    int N, bf16* __restrict__ oh, bf16* __restrict__ ol)
{
    const float* x = X + (size_t)blockIdx.x * N;
    float s = 0.0f, q = 0.0f;
    for (int i = threadIdx.x; i < N; i += 256) { float t = x[i]; s += t; q += t * t; }
    blockReduce2(s, q);
    float mu = s / N;
    float rstd = rsqrtf(q / N - mu * mu + EPSV);
    for (int i = threadIdx.x; i < N; i += 256) {
        float t = gelu_exact((x[i] - mu) * rstd * g[i] + b[i]);
        bf16 h, l; split1(t, h, l);
        oh[(size_t)blockIdx.x * N + i] = h;
        ol[(size_t)blockIdx.x * N + i] = l;
    }
}

__global__ void gate_split_k(const float* __restrict__ f1, const float* __restrict__ f2) {
    const size_t i = (size_t)blockIdx.x * 256 + threadIdx.x;
    float gv = 1.0f / (1.0f + expf(-g_gf[i]));
    float o = gv * f1[i] + (1.0f - gv) * f2[i];
    g_gf[i] = o;
    bf16 h, l; split1(o, h, l);
    g_gfh[i] = h; g_gfl[i] = l;
}

__global__ __launch_bounds__(256) void attn_k(
    const float* __restrict__ f1,
    const float* __restrict__ alng, const float* __restrict__ alnb,
    const float* __restrict__ ln1g, const float* __restrict__ ln1b)
{
    const size_t base = (size_t)blockIdx.x * DIM;
    const int tid = threadIdx.x;
    float s1 = 0.0f, s2 = 0.0f;
    #pragma unroll
    for (int j = 0; j < 8; j++) {
        int c = tid + j * 256;
        float qq = g_q[base + c];
        s1 += qq * g_k1[base + c];
        s2 += qq * g_k2[base + c];
    }
    blockReduce2(s1, s2);
    const float inv = rsqrtf((float)DIM);
    float w1 = 1.0f / (1.0f + expf((s2 - s1) * inv));
    float w2 = 1.0f - w1;

    float t[8]; float s = 0.0f, q = 0.0f;
    #pragma unroll
    for (int j = 0; j < 8; j++) {
        int c = tid + j * 256;
        float tv = g_gf[base + c] + w1 * g_v1[base + c] + w2 * g_v2[base + c];
        t[j] = tv; s += tv; q += tv * tv;
    }
    blockReduce2(s, q);
    float mu = s / DIM, rstd = rsqrtf(q / DIM - mu * mu + EPSV);

    float r[8]; s = 0.0f; q = 0.0f;
    #pragma unroll
    for (int j = 0; j < 8; j++) {
        int c = tid + j * 256;
        float gv = (t[j] - mu) * rstd * alng[c] + alnb[c];
        float rv = gv + f1[base + c];
        r[j] = rv; s += rv; q += rv * rv;
    }
    blockReduce2(s, q);
    mu = s / DIM; rstd = rsqrtf(q / DIM - mu * mu + EPSV);
    #pragma unroll
    for (int j = 0; j < 8; j++) {
        int c = tid + j * 256;
        g_r1[base + c] = (r[j] - mu) * rstd * ln1g[c] + ln1b[c];
    }
}

__global__ void zero_k() {
    int i = blockIdx.x * 256 + threadIdx.x;
    if (i < NASP * DIM) { g_sum[i] = 0.0f; g_sq[i] = 0.0f; }
    if (i < NASP) g_cnt[i] = 0.0f;
}

__global__ void cnt_k(const int* __restrict__ asp) {
    __shared__ int c[NASP];
    if (threadIdx.x < NASP) c[threadIdx.x] = 0;
    __syncthreads();
    for (int i = threadIdx.x; i < BSZ; i += blockDim.x) atomicAdd(&c[asp[i]], 1);
    __syncthreads();
    if (threadIdx.x < NASP) g_cnt[threadIdx.x] = (float)c[threadIdx.x];
}

__global__ __launch_bounds__(128) void bnstat_k(const int* __restrict__ asp) {
    int col = blockIdx.x * 128 + threadIdx.x;
    int r0 = blockIdx.y * 128;
    float m0 = 0, m1 = 0, m2 = 0, q0 = 0, q1 = 0, q2 = 0;
    for (int r = r0; r < r0 + 128; r++) {
        int a = asp[r];
        float x = g_r1[(size_t)r * DIM + col];
        float xx = x * x;
        if (a == 0)      { m0 += x; q0 += xx; }
        else if (a == 1) { m1 += x; q1 += xx; }
        else             { m2 += x; q2 += xx; }
    }
    atomicAdd(&g_sum[0 * DIM + col], m0); atomicAdd(&g_sq[0 * DIM + col], q0);
    atomicAdd(&g_sum[1 * DIM + col], m1); atomicAdd(&g_sq[1 * DIM + col], q1);
    atomicAdd(&g_sum[2 * DIM + col], m2); atomicAdd(&g_sq[2 * DIM + col], q2);
}

__global__ void bnfin_k(const float* __restrict__ bng, const float* __restrict__ bnb) {
    int i = blockIdx.x * 256 + threadIdx.x;
    if (i >= NASP * DIM) return;
    int a = i / DIM;
    float safe = fmaxf(g_cnt[a], 1.0f);
    float mean = g_sum[i] / safe;
    float var  = g_sq[i] / safe - mean * mean;
    float sc = rsqrtf(var + EPSV) * bng[i];
    g_scale[i] = sc;
    g_shift[i] = bnb[i] - mean * sc;
}

__global__ __launch_bounds__(256) void bnapply_split_k(const int* __restrict__ asp) {
    int row = blockIdx.x;
    int a = asp[row];
    bool norm = g_cnt[a] > 1.0f;
    size_t base = (size_t)row * DIM;
    for (int c = threadIdx.x; c < DIM; c += 256) {
        float x = g_r1[base + c];
        float o = norm ? fmaf(x, g_scale[a * DIM + c], g_shift[a * DIM + c]) : x;
        g_r1[base + c] = o;
        bf16 h, l; split1(o, h, l);
        g_r1h[base + c] = h; g_r1l[base + c] = l;
    }
}

__global__ __launch_bounds__(256) void final_k(
    float* __restrict__ out,
    const float* __restrict__ ln2g, const float* __restrict__ ln2b)
{
    const size_t base = (size_t)blockIdx.x * DIM;
    const int tid = threadIdx.x;
    float t[8]; float s = 0.0f, q = 0.0f;
    #pragma unroll
    for (int j = 0; j < 8; j++) {
        int c = tid + j * 256;
        float tv = g_ffn[base + c] + g_r1[base + c];
        t[j] = tv; s += tv; q += tv * tv;
    }
    blockReduce2(s, q);
    float mu = s / DIM, rstd = rsqrtf(q / DIM - mu * mu + EPSV);
    #pragma unroll
    for (int j = 0; j < 8; j++) {
        int c = tid + j * 256;
        out[base + c] = (t[j] - mu) * rstd * ln2g[c] + ln2b[c];
    }
}

// ============================ launch ============================
extern "C" void kernel_launch(void* const* d_in, const int* in_sizes, int n_in,
                              void* d_out, int out_size)
{
    (void)in_sizes; (void)n_in; (void)out_size;
    const float* f1   = (const float*)d_in[0];
    const float* f2   = (const float*)d_in[1];
    const int*   asp  = (const int*)  d_in[2];
    const float* gW1  = (const float*)d_in[3];
    const float* gb1  = (const float*)d_in[4];
    const float* gl1g = (const float*)d_in[5];
    const float* gl1b = (const float*)d_in[6];
    const float* gW2  = (const float*)d_in[7];
    const float* gb2  = (const float*)d_in[8];
    const float* gl2g = (const float*)d_in[9];
    const float* gl2b = (const float*)d_in[10];
    const float* gW3  = (const float*)d_in[11];
    const float* gb3  = (const float*)d_in[12];
    const float* qW   = (const float*)d_in[13];
    const float* qb   = (const float*)d_in[14];
    const float* kW   = (const float*)d_in[15];
    const float* kb   = (const float*)d_in[16];
    const float* vW   = (const float*)d_in[17];
    const float* vb   = (const float*)d_in[18];
    const float* alng = (const float*)d_in[19];
    const float* alnb = (const float*)d_in[20];
    const float* bng  = (const float*)d_in[21];
    const float* bnb  = (const float*)d_in[22];
    const float* ln1g = (const float*)d_in[23];
    const float* ln1b = (const float*)d_in[24];
    const float* fW1  = (const float*)d_in[25];
    const float* fb1  = (const float*)d_in[26];
    const float* fW2  = (const float*)d_in[27];
    const float* fb2  = (const float*)d_in[28];
    const float* ln2g = (const float*)d_in[29];
    const float* ln2b = (const float*)d_in[30];
    float* out = (float*)d_out;

    cudaFuncSetAttribute(gemm_mma_k, cudaFuncAttributeMaxDynamicSharedMemorySize, GEMM_SMEM_BYTES);

    float *p_h1, *p_h2, *p_gf, *p_q, *p_k1, *p_k2, *p_v1, *p_v2, *p_r1, *p_ffn;
    bf16 *p_cath, *p_catl, *p_h1h, *p_h1l, *p_h2h, *p_h2l, *p_gfh, *p_gfl;
    bf16 *p_f1h, *p_f1l, *p_f2h, *p_f2l, *p_r1h, *p_r1l, *p_hidh, *p_hidl;
    bf16 *pw_g1h, *pw_g1l, *pw_g2h, *pw_g2l, *pw_g3h, *pw_g3l;
    bf16 *pw_qh, *pw_ql, *pw_kh, *pw_kl, *pw_vh, *pw_vl, *pw_f1h, *pw_f1l, *pw_f2h, *pw_f2l;
    cudaGetSymbolAddress((void**)&p_h1, g_h1);   cudaGetSymbolAddress((void**)&p_h2, g_h2);
    cudaGetSymbolAddress((void**)&p_gf, g_gf);   cudaGetSymbolAddress((void**)&p_q, g_q);
    cudaGetSymbolAddress((void**)&p_k1, g_k1);   cudaGetSymbolAddress((void**)&p_k2, g_k2);
    cudaGetSymbolAddress((void**)&p_v1, g_v1);   cudaGetSymbolAddress((void**)&p_v2, g_v2);
    cudaGetSymbolAddress((void**)&p_r1, g_r1);   cudaGetSymbolAddress((void**)&p_ffn, g_ffn);
    cudaGetSymbolAddress((void**)&p_cath, g_cath); cudaGetSymbolAddress((void**)&p_catl, g_catl);
    cudaGetSymbolAddress((void**)&p_h1h, g_h1h); cudaGetSymbolAddress((void**)&p_h1l, g_h1l);
    cudaGetSymbolAddress((void**)&p_h2h, g_h2h); cudaGetSymbolAddress((void**)&p_h2l, g_h2l);
    cudaGetSymbolAddress((void**)&p_gfh, g_gfh); cudaGetSymbolAddress((void**)&p_gfl, g_gfl);
    cudaGetSymbolAddress((void**)&p_f1h, g_f1h); cudaGetSymbolAddress((void**)&p_f1l, g_f1l);
    cudaGetSymbolAddress((void**)&p_f2h, g_f2h); cudaGetSymbolAddress((void**)&p_f2l, g_f2l);
    cudaGetSymbolAddress((void**)&p_r1h, g_r1h); cudaGetSymbolAddress((void**)&p_r1l, g_r1l);
    cudaGetSymbolAddress((void**)&p_hidh, g_hidh); cudaGetSymbolAddress((void**)&p_hidl, g_hidl);
    cudaGetSymbolAddress((void**)&pw_g1h, w_g1h); cudaGetSymbolAddress((void**)&pw_g1l, w_g1l);
    cudaGetSymbolAddress((void**)&pw_g2h, w_g2h); cudaGetSymbolAddress((void**)&pw_g2l, w_g2l);
    cudaGetSymbolAddress((void**)&pw_g3h, w_g3h); cudaGetSymbolAddress((void**)&pw_g3l, w_g3l);
    cudaGetSymbolAddress((void**)&pw_qh, w_qh);   cudaGetSymbolAddress((void**)&pw_ql, w_ql);
    cudaGetSymbolAddress((void**)&pw_kh, w_kh);   cudaGetSymbolAddress((void**)&pw_kl, w_kl);
    cudaGetSymbolAddress((void**)&pw_vh, w_vh);   cudaGetSymbolAddress((void**)&pw_vl, w_vl);
    cudaGetSymbolAddress((void**)&pw_f1h, w_f1h); cudaGetSymbolAddress((void**)&pw_f1l, w_f1l);
    cudaGetSymbolAddress((void**)&pw_f2h, w_f2h); cudaGetSymbolAddress((void**)&pw_f2l, w_f2l);

    dim3 tb(32, 8);
    splitT_k<<<dim3(HID/32, (2*DIM)/32), tb>>>(gW1, pw_g1h, pw_g1l, 2*DIM, HID);
    splitT_k<<<dim3((HID/2)/32, HID/32), tb>>>(gW2, pw_g2h, pw_g2l, HID, HID/2);
    splitT_k<<<dim3(DIM/32, (HID/2)/32), tb>>>(gW3, pw_g3h, pw_g3l, HID/2, DIM);
    splitT_k<<<dim3(DIM/32, DIM/32), tb>>>(qW, pw_qh, pw_ql, DIM, DIM);
    splitT_k<<<dim3(DIM/32, DIM/32), tb>>>(kW, pw_kh, pw_kl, DIM, DIM);
    splitT_k<<<dim3(DIM/32, DIM/32), tb>>>(vW, pw_vh, pw_vl, DIM, DIM);
    splitT_k<<<dim3((2*DIM)/32, DIM/32), tb>>>(fW1, pw_f1h, pw_f1l, DIM, 2*DIM);
    splitT_k<<<dim3(DIM/32, (2*DIM)/32), tb>>>(fW2, pw_f2h, pw_f2l, 2*DIM, DIM);

    splitcat_k<<<dim3((2*DIM)/1024, BSZ), 256>>>(f1, f2);
    split_pair_k<<<(BSZ*DIM)/1024, 256>>>(f1, p_f1h, p_f1l);
    split_pair_k<<<(BSZ*DIM)/1024, 256>>>(f2, p_f2h, p_f2l);

    #define GEMM(A_h, A_l, B_h, B_l, bias, Cf, Chh, Cll, Mv, Nv, Kv, ep) \
        gemm_mma_k<<<dim3((Nv)/BN, (Mv)/BM), 256, GEMM_SMEM_BYTES>>>( \
            A_h, A_l, B_h, B_l, bias, Cf, Chh, Cll, Mv, Nv, Kv, ep)

    // gate MLP
    GEMM(p_cath, p_catl, pw_g1h, pw_g1l, gb1, p_h1, nullptr, nullptr, BSZ, HID, 2*DIM, 0);
    ln_gelu_split_k<<<BSZ, 256>>>(p_h1, gl1g, gl1b, HID, p_h1h, p_h1l);
    GEMM(p_h1h, p_h1l, pw_g2h, pw_g2l, gb2, p_h2, nullptr, nullptr, BSZ, HID/2, HID, 0);
    ln_gelu_split_k<<<BSZ, 256>>>(p_h2, gl2g, gl2b, HID/2, p_h2h, p_h2l);
    GEMM(p_h2h, p_h2l, pw_g3h, pw_g3l, gb3, p_gf, nullptr, nullptr, BSZ, DIM, HID/2, 0);
    gate_split_k<<<(BSZ*DIM)/256, 256>>>(f1, f2);

    // attention projections
    GEMM(p_gfh, p_gfl, pw_qh, pw_ql, qb, p_q,  nullptr, nullptr, BSZ, DIM, DIM, 0);
    GEMM(p_f1h, p_f1l, pw_kh, pw_kl, kb, p_k1, nullptr, nullptr, BSZ, DIM, DIM, 0);
    GEMM(p_f2h, p_f2l, pw_kh, pw_kl, kb, p_k2, nullptr, nullptr, BSZ, DIM, DIM, 0);
    GEMM(p_f1h, p_f1l, pw_vh, pw_vl, vb, p_v1, nullptr, nullptr, BSZ, DIM, DIM, 0);
    GEMM(p_f2h, p_f2l, pw_vh, pw_vl, vb, p_v2, nullptr, nullptr, BSZ, DIM, DIM, 0);

    attn_k<<<BSZ, 256>>>(f1, alng, alnb, ln1g, ln1b);

    zero_k<<<(NASP*DIM + 255)/256, 256>>>();
    cnt_k<<<1, 256>>>(asp);
    bnstat_k<<<dim3(DIM/128, BSZ/128), 128>>>(asp);
    bnfin_k<<<(NASP*DIM + 255)/256, 256>>>(bng, bnb);
    bnapply_split_k<<<BSZ, 256>>>(asp);

    // FFN: gelu+split fused into first GEMM epilogue
    GEMM(p_r1h, p_r1l, pw_f1h, pw_f1l, fb1, nullptr, p_hidh, p_hidl, BSZ, 2*DIM, DIM, 2);
    GEMM(p_hidh, p_hidl, pw_f2h, pw_f2l, fb2, p_ffn, nullptr, nullptr, BSZ, DIM, 2*DIM, 0);

    final_k<<<BSZ, 256>>>(out, ln2g, ln2b);
}

// round 9
// speedup vs baseline: 3.3906x; 1.2654x over previous
#include <cuda_runtime.h>
#include <cuda_bf16.h>
#include <math.h>
#include <stdint.h>

typedef __nv_bfloat16 bf16;

#define BSZ 8192
#define DIM 2048
#define HID 512
#define NASP 3
#define EPSV 1e-5f

// ---------------- GEMM tiling (mma.sync path, base ISA only) ----------------
#define BM 128
#define BN 128
#define BKC 32
#define ROWP 40                      // padded row stride (elems) -> 80B, conflict-free ldmatrix
#define ARR_BYTES (128 * ROWP * 2)   // 10240 B per tile array
#define STAGE_BYTES (4 * ARR_BYTES)  // Ah, Al, Bh, Bl
#define GEMM_SMEM_BYTES (2 * STAGE_BYTES)   // 81920

// ---------------- fp32 scratch ----------------
__device__ float g_h1[(size_t)BSZ * HID];
__device__ float g_h2[(size_t)BSZ * (HID / 2)];
__device__ float g_gf[(size_t)BSZ * DIM];
__device__ float g_qk[(size_t)BSZ * DIM];
__device__ float g_attn[(size_t)BSZ * DIM];
__device__ float g_r1[(size_t)BSZ * DIM];
__device__ float g_ffn[(size_t)BSZ * DIM];
__device__ float g_sum[NASP * DIM];
__device__ float g_sq [NASP * DIM];
__device__ float g_scale[NASP * DIM];
__device__ float g_shift[NASP * DIM];
__device__ float g_cnt[NASP];

// ---------------- bf16 split activations ----------------
__device__ bf16 g_f1h[(size_t)BSZ * DIM];
__device__ bf16 g_f1l[(size_t)BSZ * DIM];
__device__ bf16 g_f2h[(size_t)BSZ * DIM];
__device__ bf16 g_f2l[(size_t)BSZ * DIM];
__device__ bf16 g_h1h[(size_t)BSZ * HID];
__device__ bf16 g_h1l[(size_t)BSZ * HID];
__device__ bf16 g_h2h[(size_t)BSZ * (HID / 2)];
__device__ bf16 g_h2l[(size_t)BSZ * (HID / 2)];
__device__ bf16 g_gfh[(size_t)BSZ * DIM];
__device__ bf16 g_gfl[(size_t)BSZ * DIM];
__device__ bf16 g_qh [(size_t)BSZ * DIM];
__device__ bf16 g_ql [(size_t)BSZ * DIM];
__device__ bf16 g_vmh[(size_t)BSZ * DIM];
__device__ bf16 g_vml[(size_t)BSZ * DIM];
__device__ bf16 g_r1h[(size_t)BSZ * DIM];
__device__ bf16 g_r1l[(size_t)BSZ * DIM];
__device__ bf16 g_hidh[(size_t)BSZ * 2 * DIM];
__device__ bf16 g_hidl[(size_t)BSZ * 2 * DIM];

// ---------------- bf16 split weights ----------------
// transposed-split ([N,K] K-major):
__device__ bf16 w_g1h[(size_t)HID * 2 * DIM];       __device__ bf16 w_g1l[(size_t)HID * 2 * DIM];
__device__ bf16 w_g2h[(size_t)(HID/2) * HID];       __device__ bf16 w_g2l[(size_t)(HID/2) * HID];
__device__ bf16 w_g3h[(size_t)DIM * (HID/2)];       __device__ bf16 w_g3l[(size_t)DIM * (HID/2)];
__device__ bf16 w_qh [(size_t)DIM * DIM];           __device__ bf16 w_ql [(size_t)DIM * DIM];
__device__ bf16 w_vh [(size_t)DIM * DIM];           __device__ bf16 w_vl [(size_t)DIM * DIM];
__device__ bf16 w_f1h[(size_t)(2*DIM) * DIM];       __device__ bf16 w_f1l[(size_t)(2*DIM) * DIM];
__device__ bf16 w_f2h[(size_t)DIM * 2 * DIM];       __device__ bf16 w_f2l[(size_t)DIM * 2 * DIM];
// kW kept in ORIGINAL [D,D] layout (qk = q @ kW^T needs B[n,k]=kW[n][k]):
__device__ bf16 w_kh [(size_t)DIM * DIM];           __device__ bf16 w_kl [(size_t)DIM * DIM];

// ============================ helpers ============================
__device__ __forceinline__ uint32_t smem_u32(const void* p) {
    uint32_t a;
    asm("{ .reg .u64 t; cvta.to.shared.u64 t, %1; cvt.u32.u64 %0, t; }" : "=r"(a) : "l"(p));
    return a;
}
__device__ __forceinline__ void cp16(uint32_t s, const void* g) {
    asm volatile("cp.async.cg.shared.global [%0], [%1], 16;" :: "r"(s), "l"(g));
}
__device__ __forceinline__ void cp_commit() { asm volatile("cp.async.commit_group;" ::: "memory"); }
__device__ __forceinline__ void cp_wait1()  { asm volatile("cp.async.wait_group 1;" ::: "memory"); }

__device__ __forceinline__ void ldsm4(uint32_t* r, uint32_t addr) {
    asm volatile("ldmatrix.sync.aligned.m8n8.x4.shared.b16 {%0,%1,%2,%3}, [%4];"
                 : "=r"(r[0]), "=r"(r[1]), "=r"(r[2]), "=r"(r[3]) : "r"(addr));
}
__device__ __forceinline__ void mma16816(float* c, const uint32_t* a, uint32_t b0, uint32_t b1) {
    asm volatile("mma.sync.aligned.m16n8k16.row.col.f32.bf16.bf16.f32 "
                 "{%0,%1,%2,%3}, {%4,%5,%6,%7}, {%8,%9}, {%0,%1,%2,%3};"
                 : "+f"(c[0]), "+f"(c[1]), "+f"(c[2]), "+f"(c[3])
                 : "r"(a[0]), "r"(a[1]), "r"(a[2]), "r"(a[3]), "r"(b0), "r"(b1));
}

__device__ __forceinline__ float gelu_exact(float x) {
    return 0.5f * x * (1.0f + erff(x * 0.7071067811865476f));
}
__device__ __forceinline__ void split1(float v, bf16& h, bf16& l) {
    h = __float2bfloat16_rn(v);
    l = __float2bfloat16_rn(v - __bfloat162float(h));
}

// ============================ split-bf16 mma.sync GEMM ============================
// C[M,N] = (Ah+Al)[M,K] @ (Bh+Bl)^T, B arrays [N,K] K-major (mma row.col).
// Concat-A mode: if Ah2 != nullptr, columns [Ks,K) come from Ah2/Al2 (each with
// row stride As). 3-product compensated fp32 accumulation.
// epi: 0 = bias -> C fp32
//      2 = bias+gelu -> split bf16 Ch/Cl
//      3 = gate: s=sigmoid(acc+bias); o=s*F1+(1-s)*F2 -> C fp32 AND split Ch/Cl
//      4 = bias -> split bf16 Ch/Cl only
__global__ __launch_bounds__(256)
void gemm_mma_k(const bf16* __restrict__ Ah, const bf16* __restrict__ Al,
                const bf16* __restrict__ Ah2, const bf16* __restrict__ Al2,
                const bf16* __restrict__ Bh, const bf16* __restrict__ Bl,
                const float* __restrict__ bias,
                const float* __restrict__ F1, const float* __restrict__ F2,
                float* __restrict__ C, bf16* __restrict__ Ch, bf16* __restrict__ Cl,
                int M, int N, int K, int As, int Ks, int epi)
{
    extern __shared__ char smem[];
    const uint32_t sb = smem_u32(smem);

    const int tid  = threadIdx.x;
    const int wid  = tid >> 5, lane = tid & 31;
    const int mBase = blockIdx.y * BM;
    const int nBase = blockIdx.x * BN;
    const int warp_m = wid >> 2;            // 0..1 -> 64-row slab
    const int warp_n = wid & 3;             // 0..3 -> 32-col slab

    const uint32_t aLM = (uint32_t)((warp_m * 64 + (lane & 15)) * (ROWP * 2) + ((lane >> 4) << 3) * 2);
    const uint32_t bLM = (uint32_t)((warp_n * 32 + ((lane >> 4) << 3) + (lane & 7)) * (ROWP * 2)
                                    + (((lane >> 3) & 1) << 3) * 2);

    float acc[4][4][4];
    #pragma unroll
    for (int i = 0; i < 4; i++)
        #pragma unroll
        for (int j = 0; j < 4; j++)
            #pragma unroll
            for (int v = 0; v < 4; v++) acc[i][j][v] = 0.0f;

    const int rL = (tid >> 2), cL = tid & 3;
    auto fill = [&](int stage, int kt) {
        const uint32_t stB = sb + (uint32_t)stage * STAGE_BYTES;
        const bf16* A_h = Ah; const bf16* A_l = Al; int kOff = kt;
        if (Ah2 != nullptr && kt >= Ks) { A_h = Ah2; A_l = Al2; kOff = kt - Ks; }
        #pragma unroll
        for (int i = 0; i < 8; i++) {
            const int arr = i >> 1;
            const int r = rL + (i & 1) * 64;
            const bf16* g;
            if (arr == 0)      g = A_h + (size_t)(mBase + r) * As + kOff + cL * 8;
            else if (arr == 1) g = A_l + (size_t)(mBase + r) * As + kOff + cL * 8;
            else if (arr == 2) g = Bh  + (size_t)(nBase + r) * K  + kt   + cL * 8;
            else               g = Bl  + (size_t)(nBase + r) * K  + kt   + cL * 8;
            cp16(stB + (uint32_t)arr * ARR_BYTES + (uint32_t)(r * (ROWP * 2) + cL * 16), g);
        }
    };

    const int niter = K / BKC;
    fill(0, 0); cp_commit();
    if (niter > 1) fill(1, BKC);
    cp_commit();

    for (int it = 0; it < niter; ++it) {
        cp_wait1();
        __syncthreads();
        const uint32_t stB = sb + (uint32_t)(it & 1) * STAGE_BYTES;
        #pragma unroll
        for (int ks = 0; ks < 2; ks++) {
            const uint32_t ksB = (uint32_t)(ks * 32);
            const uint32_t aH = stB + 0 * ARR_BYTES + aLM + ksB;
            const uint32_t aL = stB + 1 * ARR_BYTES + aLM + ksB;
            const uint32_t bH = stB + 2 * ARR_BYTES + bLM + ksB;
            const uint32_t bL = stB + 3 * ARR_BYTES + bLM + ksB;

            uint32_t aF[4][4], bFh[2][4], bFl[2][4];
            #pragma unroll
            for (int am = 0; am < 4; am++) ldsm4(aF[am], aH + (uint32_t)(am * 16 * ROWP * 2));
            #pragma unroll
            for (int bt = 0; bt < 2; bt++) ldsm4(bFh[bt], bH + (uint32_t)(bt * 16 * ROWP * 2));
            #pragma unroll
            for (int bt = 0; bt < 2; bt++) ldsm4(bFl[bt], bL + (uint32_t)(bt * 16 * ROWP * 2));

            #pragma unroll
            for (int am = 0; am < 4; am++)
                #pragma unroll
                for (int bt = 0; bt < 2; bt++) {
                    mma16816(acc[am][bt * 2 + 0], aF[am], bFh[bt][0], bFh[bt][1]);
                    mma16816(acc[am][bt * 2 + 1], aF[am], bFh[bt][2], bFh[bt][3]);
                }
            #pragma unroll
            for (int am = 0; am < 4; am++)
                #pragma unroll
                for (int bt = 0; bt < 2; bt++) {
                    mma16816(acc[am][bt * 2 + 0], aF[am], bFl[bt][0], bFl[bt][1]);
                    mma16816(acc[am][bt * 2 + 1], aF[am], bFl[bt][2], bFl[bt][3]);
                }
            #pragma unroll
            for (int am = 0; am < 4; am++) ldsm4(aF[am], aL + (uint32_t)(am * 16 * ROWP * 2));
            #pragma unroll
            for (int am = 0; am < 4; am++)
                #pragma unroll
                for (int bt = 0; bt < 2; bt++) {
                    mma16816(acc[am][bt * 2 + 0], aF[am], bFh[bt][0], bFh[bt][1]);
                    mma16816(acc[am][bt * 2 + 1], aF[am], bFh[bt][2], bFh[bt][3]);
                }
        }
        __syncthreads();
        if (it + 2 < niter) fill(it & 1, (it + 2) * BKC);
        cp_commit();
    }

    // ---- epilogue ----
    const int rowQ = lane >> 2, colQ = (lane & 3) * 2;
    #pragma unroll
    for (int am = 0; am < 4; am++) {
        const int r0 = mBase + warp_m * 64 + am * 16 + rowQ;
        #pragma unroll
        for (int bn = 0; bn < 4; bn++) {
            const int c0 = nBase + warp_n * 32 + bn * 8 + colQ;
            const float b0 = bias ? __ldg(bias + c0) : 0.0f;
            const float b1 = bias ? __ldg(bias + c0 + 1) : 0.0f;
            float v0 = acc[am][bn][0] + b0, v1 = acc[am][bn][1] + b1;
            float v2 = acc[am][bn][2] + b0, v3 = acc[am][bn][3] + b1;
            if (epi == 2) {
                v0 = gelu_exact(v0); v1 = gelu_exact(v1);
                v2 = gelu_exact(v2); v3 = gelu_exact(v3);
            }
            if (epi == 3) {
                const size_t o00 = (size_t)r0 * N + c0, o10 = (size_t)(r0 + 8) * N + c0;
                float s0 = 1.0f / (1.0f + expf(-v0));
                float s1 = 1.0f / (1.0f + expf(-v1));
                float s2 = 1.0f / (1.0f + expf(-v2));
                float s3 = 1.0f / (1.0f + expf(-v3));
                v0 = s0 * __ldg(F1 + o00)     + (1.0f - s0) * __ldg(F2 + o00);
                v1 = s1 * __ldg(F1 + o00 + 1) + (1.0f - s1) * __ldg(F2 + o00 + 1);
                v2 = s2 * __ldg(F1 + o10)     + (1.0f - s2) * __ldg(F2 + o10);
                v3 = s3 * __ldg(F1 + o10 + 1) + (1.0f - s3) * __ldg(F2 + o10 + 1);
                *(float2*)(C + o00) = make_float2(v0, v1);
                *(float2*)(C + o10) = make_float2(v2, v3);
            }
            if (epi == 2 || epi == 3 || epi == 4) {
                bf16 h0,l0,h1,l1;
                split1(v0, h0, l0); split1(v1, h1, l1);
                __nv_bfloat162 hv, lv; hv.x = h0; hv.y = h1; lv.x = l0; lv.y = l1;
                *(__nv_bfloat162*)(Ch + (size_t)r0 * N + c0) = hv;
                *(__nv_bfloat162*)(Cl + (size_t)r0 * N + c0) = lv;
                split1(v2, h0, l0); split1(v3, h1, l1);
                hv.x = h0; hv.y = h1; lv.x = l0; lv.y = l1;
                *(__nv_bfloat162*)(Ch + (size_t)(r0 + 8) * N + c0) = hv;
                *(__nv_bfloat162*)(Cl + (size_t)(r0 + 8) * N + c0) = lv;
            } else if (epi == 0) {
                *(float2*)(C + (size_t)r0 * N + c0)       = make_float2(v0, v1);
                *(float2*)(C + (size_t)(r0 + 8) * N + c0) = make_float2(v2, v3);
            }
        }
    }
}

// ============================ pre-pass kernels ============================

// W [K,N] fp32 -> Wt hi/lo [N,K] bf16. 32x32 tiles, block (32,8).
__global__ void splitT_k(const float* __restrict__ W, bf16* __restrict__ ht,
                         bf16* __restrict__ lt, int K, int N)
{
    __shared__ float t[32][33];
    const int n0 = blockIdx.x * 32, k0 = blockIdx.y * 32;
    const int tx = threadIdx.x, ty = threadIdx.y;
    #pragma unroll
    for (int i = 0; i < 4; i++)
        t[ty + i * 8][tx] = W[(size_t)(k0 + ty + i * 8) * N + n0 + tx];
    __syncthreads();
    #pragma unroll
    for (int i = 0; i < 4; i++) {
        const int n = ty + i * 8;
        float v = t[tx][n];
        bf16 h, l; split1(v, h, l);
        const size_t o = (size_t)(n0 + n) * K + k0 + tx;
        ht[o] = h; lt[o] = l;
    }
}

__global__ void split_pair_k(const float* __restrict__ x, bf16* __restrict__ h,
                             bf16* __restrict__ l)
{
    const size_t i4 = ((size_t)blockIdx.x * 256 + threadIdx.x) * 4;
    float4 v = *(const float4*)(x + i4);
    bf16 h0,l0,h1,l1,h2,l2,h3,l3;
    split1(v.x,h0,l0); split1(v.y,h1,l1); split1(v.z,h2,l2); split1(v.w,h3,l3);
    __nv_bfloat162 a,b,c,d;
    a.x=h0;a.y=h1; b.x=h2;b.y=h3; c.x=l0;c.y=l1; d.x=l2;d.y=l3;
    *(__nv_bfloat162*)(h + i4)     = a; *(__nv_bfloat162*)(h + i4 + 2) = b;
    *(__nv_bfloat162*)(l + i4)     = c; *(__nv_bfloat162*)(l + i4 + 2) = d;
}

// ============================ elementwise / rowwise ============================

__device__ __forceinline__ void blockReduce2(float& a, float& b) {
    __shared__ float sb[16];
    #pragma unroll
    for (int o = 16; o > 0; o >>= 1) {
        a += __shfl_down_sync(0xffffffffu, a, o);
        b += __shfl_down_sync(0xffffffffu, b, o);
    }
    int lane = threadIdx.x & 31, w = threadIdx.x >> 5;
    __syncthreads();
    if (lane == 0) { sb[w] = a; sb[8 + w] = b; }
    __syncthreads();
    if (w == 0) {
        a = (lane < 8) ? sb[lane] : 0.0f;
        b = (lane < 8) ? sb[8 + lane] : 0.0f;
        #pragma unroll
        for (int o = 4; o > 0; o >>= 1) {
            a += __shfl_down_sync(0xffffffffu, a, o);
            b += __shfl_down_sync(0xffffffffu, b, o);
        }
        if (lane == 0) { sb[0] = a; sb[8] = b; }
    }
    __syncthreads();
    a = sb[0]; b = sb[8];
}

__global__ __launch_bounds__(256) void ln_gelu_split_k(
    const float* __restrict__ X, const float* __restrict__ g, const float* __restrict__ b,
    int N, bf16* __restrict__ oh, bf16* __restrict__ ol)
{
    const float* x = X + (size_t)blockIdx.x * N;
    float s = 0.0f, q = 0.0f;
    for (int i = threadIdx.x; i < N; i += 256) { float t = x[i]; s += t; q += t * t; }
    blockReduce2(s, q);
    float mu = s / N;
    float rstd = rsqrtf(q / N - mu * mu + EPSV);
    for (int i = threadIdx.x; i < N; i += 256) {
        float t = gelu_exact((x[i] - mu) * rstd * g[i] + b[i]);
        bf16 h, l; split1(t, h, l);
        oh[(size_t)blockIdx.x * N + i] = h;
        ol[(size_t)blockIdx.x * N + i] = l;
    }
}

// per row: s1 = qk.f1, s2 = qk.f2 -> softmax2 -> vmix = w1 f1 + w2 f2 (split bf16)
__global__ __launch_bounds__(256) void score_vmix_k(
    const float* __restrict__ f1, const float* __restrict__ f2)
{
    const size_t base = (size_t)blockIdx.x * DIM;
    const int tid = threadIdx.x;
    float t1[8], t2[8];
    float s1 = 0.0f, s2 = 0.0f;
    #pragma unroll
    for (int j = 0; j < 8; j++) {
        int c = tid + j * 256;
        float qq = g_qk[base + c];
        t1[j] = f1[base + c]; t2[j] = f2[base + c];
        s1 += qq * t1[j];
        s2 += qq * t2[j];
    }
    blockReduce2(s1, s2);
    const float inv = rsqrtf((float)DIM);
    float w1 = 1.0f / (1.0f + expf((s2 - s1) * inv));
    float w2 = 1.0f - w1;
    #pragma unroll
    for (int j = 0; j < 8; j++) {
        int c = tid + j * 256;
        float v = w1 * t1[j] + w2 * t2[j];
        bf16 h, l; split1(v, h, l);
        g_vmh[base + c] = h; g_vml[base + c] = l;
    }
}

// t = gf + attn -> LN(aln) -> +f1 -> LN(ln1) -> r1
__global__ __launch_bounds__(256) void attn2_k(
    const float* __restrict__ f1,
    const float* __restrict__ alng, const float* __restrict__ alnb,
    const float* __restrict__ ln1g, const float* __restrict__ ln1b)
{
    const size_t base = (size_t)blockIdx.x * DIM;
    const int tid = threadIdx.x;
    float t[8]; float s = 0.0f, q = 0.0f;
    #pragma unroll
    for (int j = 0; j < 8; j++) {
        int c = tid + j * 256;
        float tv = g_gf[base + c] + g_attn[base + c];
        t[j] = tv; s += tv; q += tv * tv;
    }
    blockReduce2(s, q);
    float mu = s / DIM, rstd = rsqrtf(q / DIM - mu * mu + EPSV);

    float r[8]; s = 0.0f; q = 0.0f;
    #pragma unroll
    for (int j = 0; j < 8; j++) {
        int c = tid + j * 256;
        float gv = (t[j] - mu) * rstd * alng[c] + alnb[c];
        float rv = gv + f1[base + c];
        r[j] = rv; s += rv; q += rv * rv;
    }
    blockReduce2(s, q);
    mu = s / DIM; rstd = rsqrtf(q / DIM - mu * mu + EPSV);
    #pragma unroll
    for (int j = 0; j < 8; j++) {
        int c = tid + j * 256;
        g_r1[base + c] = (r[j] - mu) * rstd * ln1g[c] + ln1b[c];
    }
}

__global__ void zero_k() {
    int i = blockIdx.x * 256 + threadIdx.x;
    if (i < NASP * DIM) { g_sum[i] = 0.0f; g_sq[i] = 0.0f; }
    if (i < NASP) g_cnt[i] = 0.0f;
}

__global__ void cnt_k(const int* __restrict__ asp) {
    __shared__ int c[NASP];
    if (threadIdx.x < NASP) c[threadIdx.x] = 0;
    __syncthreads();
    for (int i = threadIdx.x; i < BSZ; i += blockDim.x) atomicAdd(&c[asp[i]], 1);
    __syncthreads();
    if (threadIdx.x < NASP) g_cnt[threadIdx.x] = (float)c[threadIdx.x];
}

__global__ __launch_bounds__(128) void bnstat_k(const int* __restrict__ asp) {
    int col = blockIdx.x * 128 + threadIdx.x;
    int r0 = blockIdx.y * 128;
    float m0 = 0, m1 = 0, m2 = 0, q0 = 0, q1 = 0, q2 = 0;
    for (int r = r0; r < r0 + 128; r++) {
        int a = asp[r];
        float x = g_r1[(size_t)r * DIM + col];
        float xx = x * x;
        if (a == 0)      { m0 += x; q0 += xx; }
        else if (a == 1) { m1 += x; q1 += xx; }
        else             { m2 += x; q2 += xx; }
    }
    atomicAdd(&g_sum[0 * DIM + col], m0); atomicAdd(&g_sq[0 * DIM + col], q0);
    atomicAdd(&g_sum[1 * DIM + col], m1); atomicAdd(&g_sq[1 * DIM + col], q1);
    atomicAdd(&g_sum[2 * DIM + col], m2); atomicAdd(&g_sq[2 * DIM + col], q2);
}

__global__ void bnfin_k(const float* __restrict__ bng, const float* __restrict__ bnb) {
    int i = blockIdx.x * 256 + threadIdx.x;
    if (i >= NASP * DIM) return;
    int a = i / DIM;
    float safe = fmaxf(g_cnt[a], 1.0f);
    float mean = g_sum[i] / safe;
    float var  = g_sq[i] / safe - mean * mean;
    float sc = rsqrtf(var + EPSV) * bng[i];
    g_scale[i] = sc;
    g_shift[i] = bnb[i] - mean * sc;
}

__global__ __launch_bounds__(256) void bnapply_split_k(const int* __restrict__ asp) {
    int row = blockIdx.x;
    int a = asp[row];
    bool norm = g_cnt[a] > 1.0f;
    size_t base = (size_t)row * DIM;
    for (int c = threadIdx.x; c < DIM; c += 256) {
        float x = g_r1[base + c];
        float o = norm ? fmaf(x, g_scale[a * DIM + c], g_shift[a * DIM + c]) : x;
        g_r1[base + c] = o;
        bf16 h, l; split1(o, h, l);
        g_r1h[base + c] = h; g_r1l[base + c] = l;
    }
}

__global__ __launch_bounds__(256) void final_k(
    float* __restrict__ out,
    const float* __restrict__ ln2g, const float* __restrict__ ln2b)
{
    const size_t base = (size_t)blockIdx.x * DIM;
    const int tid = threadIdx.x;
    float t[8]; float s = 0.0f, q = 0.0f;
    #pragma unroll
    for (int j = 0; j < 8; j++) {
        int c = tid + j * 256;
        float tv = g_ffn[base + c] + g_r1[base + c];
        t[j] = tv; s += tv; q += tv * tv;
    }
    blockReduce2(s, q);
    float mu = s / DIM, rstd = rsqrtf(q / DIM - mu * mu + EPSV);
    #pragma unroll
    for (int j = 0; j < 8; j++) {
        int c = tid + j * 256;
        out[base + c] = (t[j] - mu) * rstd * ln2g[c] + ln2b[c];
    }
}

// ============================ launch ============================
extern "C" void kernel_launch(void* const* d_in, const int* in_sizes, int n_in,
                              void* d_out, int out_size)
{
    (void)in_sizes; (void)n_in; (void)out_size;
    const float* f1   = (const float*)d_in[0];
    const float* f2   = (const float*)d_in[1];
    const int*   asp  = (const int*)  d_in[2];
    const float* gW1  = (const float*)d_in[3];
    const float* gb1  = (const float*)d_in[4];
    const float* gl1g = (const float*)d_in[5];
    const float* gl1b = (const float*)d_in[6];
    const float* gW2  = (const float*)d_in[7];
    const float* gb2  = (const float*)d_in[8];
    const float* gl2g = (const float*)d_in[9];
    const float* gl2b = (const float*)d_in[10];
    const float* gW3  = (const float*)d_in[11];
    const float* gb3  = (const float*)d_in[12];
    const float* qW   = (const float*)d_in[13];
    const float* qb   = (const float*)d_in[14];
    const float* kW   = (const float*)d_in[15];
    const float* vW   = (const float*)d_in[17];
    const float* vb   = (const float*)d_in[18];
    const float* alng = (const float*)d_in[19];
    const float* alnb = (const float*)d_in[20];
    const float* bng  = (const float*)d_in[21];
    const float* bnb  = (const float*)d_in[22];
    const float* ln1g = (const float*)d_in[23];
    const float* ln1b = (const float*)d_in[24];
    const float* fW1  = (const float*)d_in[25];
    const float* fb1  = (const float*)d_in[26];
    const float* fW2  = (const float*)d_in[27];
    const float* fb2  = (const float*)d_in[28];
    const float* ln2g = (const float*)d_in[29];
    const float* ln2b = (const float*)d_in[30];
    float* out = (float*)d_out;

    cudaFuncSetAttribute(gemm_mma_k, cudaFuncAttributeMaxDynamicSharedMemorySize, GEMM_SMEM_BYTES);

    float *p_h1, *p_h2, *p_gf, *p_qk, *p_attn, *p_r1, *p_ffn;
    bf16 *p_f1h, *p_f1l, *p_f2h, *p_f2l, *p_h1h, *p_h1l, *p_h2h, *p_h2l;
    bf16 *p_gfh, *p_gfl, *p_qh, *p_ql, *p_vmh, *p_vml, *p_r1h, *p_r1l, *p_hidh, *p_hidl;
    bf16 *pw_g1h, *pw_g1l, *pw_g2h, *pw_g2l, *pw_g3h, *pw_g3l;
    bf16 *pw_qh, *pw_ql, *pw_kh, *pw_kl, *pw_vh, *pw_vl, *pw_f1h, *pw_f1l, *pw_f2h, *pw_f2l;
    cudaGetSymbolAddress((void**)&p_h1, g_h1);   cudaGetSymbolAddress((void**)&p_h2, g_h2);
    cudaGetSymbolAddress((void**)&p_gf, g_gf);   cudaGetSymbolAddress((void**)&p_qk, g_qk);
    cudaGetSymbolAddress((void**)&p_attn, g_attn);
    cudaGetSymbolAddress((void**)&p_r1, g_r1);   cudaGetSymbolAddress((void**)&p_ffn, g_ffn);
    cudaGetSymbolAddress((void**)&p_f1h, g_f1h); cudaGetSymbolAddress((void**)&p_f1l, g_f1l);
    cudaGetSymbolAddress((void**)&p_f2h, g_f2h); cudaGetSymbolAddress((void**)&p_f2l, g_f2l);
    cudaGetSymbolAddress((void**)&p_h1h, g_h1h); cudaGetSymbolAddress((void**)&p_h1l, g_h1l);
    cudaGetSymbolAddress((void**)&p_h2h, g_h2h); cudaGetSymbolAddress((void**)&p_h2l, g_h2l);
    cudaGetSymbolAddress((void**)&p_gfh, g_gfh); cudaGetSymbolAddress((void**)&p_gfl, g_gfl);
    cudaGetSymbolAddress((void**)&p_qh, g_qh);   cudaGetSymbolAddress((void**)&p_ql, g_ql);
    cudaGetSymbolAddress((void**)&p_vmh, g_vmh); cudaGetSymbolAddress((void**)&p_vml, g_vml);
    cudaGetSymbolAddress((void**)&p_r1h, g_r1h); cudaGetSymbolAddress((void**)&p_r1l, g_r1l);
    cudaGetSymbolAddress((void**)&p_hidh, g_hidh); cudaGetSymbolAddress((void**)&p_hidl, g_hidl);
    cudaGetSymbolAddress((void**)&pw_g1h, w_g1h); cudaGetSymbolAddress((void**)&pw_g1l, w_g1l);
    cudaGetSymbolAddress((void**)&pw_g2h, w_g2h); cudaGetSymbolAddress((void**)&pw_g2l, w_g2l);
    cudaGetSymbolAddress((void**)&pw_g3h, w_g3h); cudaGetSymbolAddress((void**)&pw_g3l, w_g3l);
    cudaGetSymbolAddress((void**)&pw_qh, w_qh);   cudaGetSymbolAddress((void**)&pw_ql, w_ql);
    cudaGetSymbolAddress((void**)&pw_kh, w_kh);   cudaGetSymbolAddress((void**)&pw_kl, w_kl);
    cudaGetSymbolAddress((void**)&pw_vh, w_vh);   cudaGetSymbolAddress((void**)&pw_vl, w_vl);
    cudaGetSymbolAddress((void**)&pw_f1h, w_f1h); cudaGetSymbolAddress((void**)&pw_f1l, w_f1l);
    cudaGetSymbolAddress((void**)&pw_f2h, w_f2h); cudaGetSymbolAddress((void**)&pw_f2l, w_f2l);

    dim3 tb(32, 8);
    splitT_k<<<dim3(HID/32, (2*DIM)/32), tb>>>(gW1, pw_g1h, pw_g1l, 2*DIM, HID);
    splitT_k<<<dim3((HID/2)/32, HID/32), tb>>>(gW2, pw_g2h, pw_g2l, HID, HID/2);
    splitT_k<<<dim3(DIM/32, (HID/2)/32), tb>>>(gW3, pw_g3h, pw_g3l, HID/2, DIM);
    splitT_k<<<dim3(DIM/32, DIM/32), tb>>>(qW, pw_qh, pw_ql, DIM, DIM);
    splitT_k<<<dim3(DIM/32, DIM/32), tb>>>(vW, pw_vh, pw_vl, DIM, DIM);
    splitT_k<<<dim3((2*DIM)/32, DIM/32), tb>>>(fW1, pw_f1h, pw_f1l, DIM, 2*DIM);
    splitT_k<<<dim3(DIM/32, (2*DIM)/32), tb>>>(fW2, pw_f2h, pw_f2l, 2*DIM, DIM);
    split_pair_k<<<(DIM*DIM)/1024, 256>>>(kW, pw_kh, pw_kl);   // kW kept [D,D] as-is

    split_pair_k<<<(BSZ*DIM)/1024, 256>>>(f1, p_f1h, p_f1l);
    split_pair_k<<<(BSZ*DIM)/1024, 256>>>(f2, p_f2h, p_f2l);

    #define GEMM(A_h, A_l, A2h, A2l, B_h, B_l, bias, Fa, Fb, Cf, Chh, Cll, Mv, Nv, Kv, Asv, Ksv, ep) \
        gemm_mma_k<<<dim3((Nv)/BN, (Mv)/BM), 256, GEMM_SMEM_BYTES>>>( \
            A_h, A_l, A2h, A2l, B_h, B_l, bias, Fa, Fb, Cf, Chh, Cll, Mv, Nv, Kv, Asv, Ksv, ep)

    // gate MLP (G1 reads [f1|f2] splits directly via concat-A mode)
    GEMM(p_f1h, p_f1l, p_f2h, p_f2l, pw_g1h, pw_g1l, gb1, nullptr, nullptr,
         p_h1, nullptr, nullptr, BSZ, HID, 2*DIM, DIM, DIM, 0);
    ln_gelu_split_k<<<BSZ, 256>>>(p_h1, gl1g, gl1b, HID, p_h1h, p_h1l);
    GEMM(p_h1h, p_h1l, nullptr, nullptr, pw_g2h, pw_g2l, gb2, nullptr, nullptr,
         p_h2, nullptr, nullptr, BSZ, HID/2, HID, HID, 0, 0);
    ln_gelu_split_k<<<BSZ, 256>>>(p_h2, gl2g, gl2b, HID/2, p_h2h, p_h2l);
    // G3: gate fused -> gf fp32 + split
    GEMM(p_h2h, p_h2l, nullptr, nullptr, pw_g3h, pw_g3l, gb3, f1, f2,
         p_gf, p_gfh, p_gfl, BSZ, DIM, HID/2, HID/2, 0, 3);

    // attention: q -> qk -> scores/vmix -> v-projection
    GEMM(p_gfh, p_gfl, nullptr, nullptr, pw_qh, pw_ql, qb, nullptr, nullptr,
         nullptr, p_qh, p_ql, BSZ, DIM, DIM, DIM, 0, 4);
    GEMM(p_qh, p_ql, nullptr, nullptr, pw_kh, pw_kl, nullptr, nullptr, nullptr,
         p_qk, nullptr, nullptr, BSZ, DIM, DIM, DIM, 0, 0);
    score_vmix_k<<<BSZ, 256>>>(f1, f2);
    GEMM(p_vmh, p_vml, nullptr, nullptr, pw_vh, pw_vl, vb, nullptr, nullptr,
         p_attn, nullptr, nullptr, BSZ, DIM, DIM, DIM, 0, 0);

    attn2_k<<<BSZ, 256>>>(f1, alng, alnb, ln1g, ln1b);

    // aspect BN
    zero_k<<<(NASP*DIM + 255)/256, 256>>>();
    cnt_k<<<1, 256>>>(asp);
    bnstat_k<<<dim3(DIM/128, BSZ/128), 128>>>(asp);
    bnfin_k<<<(NASP*DIM + 255)/256, 256>>>(bng, bnb);
    bnapply_split_k<<<BSZ, 256>>>(asp);

    // FFN
    GEMM(p_r1h, p_r1l, nullptr, nullptr, pw_f1h, pw_f1l, fb1, nullptr, nullptr,
         nullptr, p_hidh, p_hidl, BSZ, 2*DIM, DIM, DIM, 0, 2);
    GEMM(p_hidh, p_hidl, nullptr, nullptr, pw_f2h, pw_f2l, fb2, nullptr, nullptr,
         p_ffn, nullptr, nullptr, BSZ, DIM, 2*DIM, 2*DIM, 0, 0);

    final_k<<<BSZ, 256>>>(out, ln2g, ln2b);
}

// round 11
// speedup vs baseline: 3.6845x; 1.0867x over previous
#include <cuda_runtime.h>
#include <cuda_bf16.h>
#include <math.h>
#include <stdint.h>

typedef __nv_bfloat16 bf16;

#define BSZ 8192
#define DIM 2048
#define HID 512
#define NASP 3
#define EPSV 1e-5f

// ---------------- GEMM tiling (mma.sync path, base ISA only) ----------------
#define BM 128
#define BN 128
#define BKC 32
#define ROWP 40                      // padded row stride (elems) -> 80B, conflict-free ldmatrix
#define ARR_BYTES (128 * ROWP * 2)   // 10240 B per tile array
#define STAGE_BYTES (4 * ARR_BYTES)  // Ah, Al, Bh, Bl
#define GEMM_SMEM_BYTES (2 * STAGE_BYTES)   // 81920

// ---------------- fp32 scratch ----------------
__device__ float g_h1[(size_t)BSZ * HID];
__device__ float g_h2[(size_t)BSZ * (HID / 2)];
__device__ float g_gf[(size_t)BSZ * DIM];
__device__ float g_qk[(size_t)BSZ * DIM];
__device__ float g_attn[(size_t)BSZ * DIM];
__device__ float g_r1[(size_t)BSZ * DIM];
__device__ float g_ffn[(size_t)BSZ * DIM];
__device__ float g_kqb[DIM];
__device__ float g_sum[NASP * DIM];
__device__ float g_sq [NASP * DIM];
__device__ float g_scale[NASP * DIM];
__device__ float g_shift[NASP * DIM];
__device__ float g_cnt[NASP];

// ---------------- bf16 split activations ----------------
__device__ bf16 g_f1h[(size_t)BSZ * DIM];
__device__ bf16 g_f1l[(size_t)BSZ * DIM];
__device__ bf16 g_f2h[(size_t)BSZ * DIM];
__device__ bf16 g_f2l[(size_t)BSZ * DIM];
__device__ bf16 g_h1h[(size_t)BSZ * HID];
__device__ bf16 g_h1l[(size_t)BSZ * HID];
__device__ bf16 g_h2h[(size_t)BSZ * (HID / 2)];
__device__ bf16 g_h2l[(size_t)BSZ * (HID / 2)];
__device__ bf16 g_gfh[(size_t)BSZ * DIM];
__device__ bf16 g_gfl[(size_t)BSZ * DIM];
__device__ bf16 g_vmh[(size_t)BSZ * DIM];
__device__ bf16 g_vml[(size_t)BSZ * DIM];
__device__ bf16 g_r1h[(size_t)BSZ * DIM];
__device__ bf16 g_r1l[(size_t)BSZ * DIM];
__device__ bf16 g_hidh[(size_t)BSZ * 2 * DIM];
__device__ bf16 g_hidl[(size_t)BSZ * 2 * DIM];

// ---------------- bf16 split weights ----------------
// transposed-split ([N,K] K-major):
__device__ bf16 w_g1h[(size_t)HID * 2 * DIM];       __device__ bf16 w_g1l[(size_t)HID * 2 * DIM];
__device__ bf16 w_g2h[(size_t)(HID/2) * HID];       __device__ bf16 w_g2l[(size_t)(HID/2) * HID];
__device__ bf16 w_g3h[(size_t)DIM * (HID/2)];       __device__ bf16 w_g3l[(size_t)DIM * (HID/2)];
__device__ bf16 w_vh [(size_t)DIM * DIM];           __device__ bf16 w_vl [(size_t)DIM * DIM];
__device__ bf16 w_f1h[(size_t)(2*DIM) * DIM];       __device__ bf16 w_f1l[(size_t)(2*DIM) * DIM];
__device__ bf16 w_f2h[(size_t)DIM * 2 * DIM];       __device__ bf16 w_f2l[(size_t)DIM * 2 * DIM];
// kW, qW in ORIGINAL [D,D] layout (plain split, no transpose):
__device__ bf16 w_kh [(size_t)DIM * DIM];           __device__ bf16 w_kl [(size_t)DIM * DIM];
__device__ bf16 w_qoh[(size_t)DIM * DIM];           __device__ bf16 w_qol[(size_t)DIM * DIM];
// Mt = kW @ qW^T, split bf16 ([n,d] row-major = B-operand layout for qk GEMM)
__device__ bf16 m_th [(size_t)DIM * DIM];           __device__ bf16 m_tl [(size_t)DIM * DIM];

// ============================ helpers ============================
__device__ __forceinline__ uint32_t smem_u32(const void* p) {
    uint32_t a;
    asm("{ .reg .u64 t; cvta.to.shared.u64 t, %1; cvt.u32.u64 %0, t; }" : "=r"(a) : "l"(p));
    return a;
}
__device__ __forceinline__ void cp16(uint32_t s, const void* g) {
    asm volatile("cp.async.cg.shared.global [%0], [%1], 16;" :: "r"(s), "l"(g));
}
__device__ __forceinline__ void cp_commit() { asm volatile("cp.async.commit_group;" ::: "memory"); }
__device__ __forceinline__ void cp_wait1()  { asm volatile("cp.async.wait_group 1;" ::: "memory"); }

__device__ __forceinline__ void ldsm4(uint32_t* r, uint32_t addr) {
    asm volatile("ldmatrix.sync.aligned.m8n8.x4.shared.b16 {%0,%1,%2,%3}, [%4];"
                 : "=r"(r[0]), "=r"(r[1]), "=r"(r[2]), "=r"(r[3]) : "r"(addr));
}
__device__ __forceinline__ void mma16816(float* c, const uint32_t* a, uint32_t b0, uint32_t b1) {
    asm volatile("mma.sync.aligned.m16n8k16.row.col.f32.bf16.bf16.f32 "
                 "{%0,%1,%2,%3}, {%4,%5,%6,%7}, {%8,%9}, {%0,%1,%2,%3};"
                 : "+f"(c[0]), "+f"(c[1]), "+f"(c[2]), "+f"(c[3])
                 : "r"(a[0]), "r"(a[1]), "r"(a[2]), "r"(a[3]), "r"(b0), "r"(b1));
}

__device__ __forceinline__ float gelu_exact(float x) {
    return 0.5f * x * (1.0f + erff(x * 0.7071067811865476f));
}
__device__ __forceinline__ void split1(float v, bf16& h, bf16& l) {
    h = __float2bfloat16_rn(v);
    l = __float2bfloat16_rn(v - __bfloat162float(h));
}

// ============================ split-bf16 mma.sync GEMM ============================
// C[M,N] = (Ah+Al)[M,K] @ (Bh+Bl)^T, B arrays [N,K] K-major (mma row.col).
// Concat-A mode: if Ah2 != nullptr, columns [Ks,K) come from Ah2/Al2 (each with
// row stride As). 3-product compensated fp32 accumulation.
// epi: 0 = bias -> C fp32
//      2 = bias+gelu -> split bf16 Ch/Cl
//      3 = gate: s=sigmoid(acc+bias); o=s*F1+(1-s)*F2 -> C fp32 AND split Ch/Cl
//      4 = bias -> split bf16 Ch/Cl only
__global__ __launch_bounds__(256)
void gemm_mma_k(const bf16* __restrict__ Ah, const bf16* __restrict__ Al,
                const bf16* __restrict__ Ah2, const bf16* __restrict__ Al2,
                const bf16* __restrict__ Bh, const bf16* __restrict__ Bl,
                const float* __restrict__ bias,
                const float* __restrict__ F1, const float* __restrict__ F2,
                float* __restrict__ C, bf16* __restrict__ Ch, bf16* __restrict__ Cl,
                int M, int N, int K, int As, int Ks, int epi)
{
    extern __shared__ char smem[];
    const uint32_t sb = smem_u32(smem);

    const int tid  = threadIdx.x;
    const int wid  = tid >> 5, lane = tid & 31;
    const int mBase = blockIdx.y * BM;
    const int nBase = blockIdx.x * BN;
    const int warp_m = wid >> 2;            // 0..1 -> 64-row slab
    const int warp_n = wid & 3;             // 0..3 -> 32-col slab

    const uint32_t aLM = (uint32_t)((warp_m * 64 + (lane & 15)) * (ROWP * 2) + ((lane >> 4) << 3) * 2);
    const uint32_t bLM = (uint32_t)((warp_n * 32 + ((lane >> 4) << 3) + (lane & 7)) * (ROWP * 2)
                                    + (((lane >> 3) & 1) << 3) * 2);

    float acc[4][4][4];
    #pragma unroll
    for (int i = 0; i < 4; i++)
        #pragma unroll
        for (int j = 0; j < 4; j++)
            #pragma unroll
            for (int v = 0; v < 4; v++) acc[i][j][v] = 0.0f;

    const int rL = (tid >> 2), cL = tid & 3;
    auto fill = [&](int stage, int kt) {
        const uint32_t stB = sb + (uint32_t)stage * STAGE_BYTES;
        const bf16* A_h = Ah; const bf16* A_l = Al; int kOff = kt;
        if (Ah2 != nullptr && kt >= Ks) { A_h = Ah2; A_l = Al2; kOff = kt - Ks; }
        #pragma unroll
        for (int i = 0; i < 8; i++) {
            const int arr = i >> 1;
            const int r = rL + (i & 1) * 64;
            const bf16* g;
            if (arr == 0)      g = A_h + (size_t)(mBase + r) * As + kOff + cL * 8;
            else if (arr == 1) g = A_l + (size_t)(mBase + r) * As + kOff + cL * 8;
            else if (arr == 2) g = Bh  + (size_t)(nBase + r) * K  + kt   + cL * 8;
            else               g = Bl  + (size_t)(nBase + r) * K  + kt   + cL * 8;
            cp16(stB + (uint32_t)arr * ARR_BYTES + (uint32_t)(r * (ROWP * 2) + cL * 16), g);
        }
    };

    const int niter = K / BKC;
    fill(0, 0); cp_commit();
    if (niter > 1) fill(1, BKC);
    cp_commit();

    for (int it = 0; it < niter; ++it) {
        cp_wait1();
        __syncthreads();
        const uint32_t stB = sb + (uint32_t)(it & 1) * STAGE_BYTES;
        #pragma unroll
        for (int ks = 0; ks < 2; ks++) {
            const uint32_t ksB = (uint32_t)(ks * 32);
            const uint32_t aH = stB + 0 * ARR_BYTES + aLM + ksB;
            const uint32_t aL = stB + 1 * ARR_BYTES + aLM + ksB;
            const uint32_t bH = stB + 2 * ARR_BYTES + bLM + ksB;
            const uint32_t bL = stB + 3 * ARR_BYTES + bLM + ksB;

            uint32_t aF[4][4], bFh[2][4], bFl[2][4];
            #pragma unroll
            for (int am = 0; am < 4; am++) ldsm4(aF[am], aH + (uint32_t)(am * 16 * ROWP * 2));
            #pragma unroll
            for (int bt = 0; bt < 2; bt++) ldsm4(bFh[bt], bH + (uint32_t)(bt * 16 * ROWP * 2));
            #pragma unroll
            for (int bt = 0; bt < 2; bt++) ldsm4(bFl[bt], bL + (uint32_t)(bt * 16 * ROWP * 2));

            #pragma unroll
            for (int am = 0; am < 4; am++)
                #pragma unroll
                for (int bt = 0; bt < 2; bt++) {
                    mma16816(acc[am][bt * 2 + 0], aF[am], bFh[bt][0], bFh[bt][1]);
                    mma16816(acc[am][bt * 2 + 1], aF[am], bFh[bt][2], bFh[bt][3]);
                }
            #pragma unroll
            for (int am = 0; am < 4; am++)
                #pragma unroll
                for (int bt = 0; bt < 2; bt++) {
                    mma16816(acc[am][bt * 2 + 0], aF[am], bFl[bt][0], bFl[bt][1]);
                    mma16816(acc[am][bt * 2 + 1], aF[am], bFl[bt][2], bFl[bt][3]);
                }
            #pragma unroll
            for (int am = 0; am < 4; am++) ldsm4(aF[am], aL + (uint32_t)(am * 16 * ROWP * 2));
            #pragma unroll
            for (int am = 0; am < 4; am++)
                #pragma unroll
                for (int bt = 0; bt < 2; bt++) {
                    mma16816(acc[am][bt * 2 + 0], aF[am], bFh[bt][0], bFh[bt][1]);
                    mma16816(acc[am][bt * 2 + 1], aF[am], bFh[bt][2], bFh[bt][3]);
                }
        }
        __syncthreads();
        if (it + 2 < niter) fill(it & 1, (it + 2) * BKC);
        cp_commit();
    }

    // ---- epilogue ----
    const int rowQ = lane >> 2, colQ = (lane & 3) * 2;
    #pragma unroll
    for (int am = 0; am < 4; am++) {
        const int r0 = mBase + warp_m * 64 + am * 16 + rowQ;
        #pragma unroll
        for (int bn = 0; bn < 4; bn++) {
            const int c0 = nBase + warp_n * 32 + bn * 8 + colQ;
            const float b0 = bias ? __ldg(bias + c0) : 0.0f;
            const float b1 = bias ? __ldg(bias + c0 + 1) : 0.0f;
            float v0 = acc[am][bn][0] + b0, v1 = acc[am][bn][1] + b1;
            float v2 = acc[am][bn][2] + b0, v3 = acc[am][bn][3] + b1;
            if (epi == 2) {
                v0 = gelu_exact(v0); v1 = gelu_exact(v1);
                v2 = gelu_exact(v2); v3 = gelu_exact(v3);
            }
            if (epi == 3) {
                const size_t o00 = (size_t)r0 * N + c0, o10 = (size_t)(r0 + 8) * N + c0;
                float s0 = 1.0f / (1.0f + expf(-v0));
                float s1 = 1.0f / (1.0f + expf(-v1));
                float s2 = 1.0f / (1.0f + expf(-v2));
                float s3 = 1.0f / (1.0f + expf(-v3));
                v0 = s0 * __ldg(F1 + o00)     + (1.0f - s0) * __ldg(F2 + o00);
                v1 = s1 * __ldg(F1 + o00 + 1) + (1.0f - s1) * __ldg(F2 + o00 + 1);
                v2 = s2 * __ldg(F1 + o10)     + (1.0f - s2) * __ldg(F2 + o10);
                v3 = s3 * __ldg(F1 + o10 + 1) + (1.0f - s3) * __ldg(F2 + o10 + 1);
                *(float2*)(C + o00) = make_float2(v0, v1);
                *(float2*)(C + o10) = make_float2(v2, v3);
            }
            if (epi == 2 || epi == 3 || epi == 4) {
                bf16 h0,l0,h1,l1;
                split1(v0, h0, l0); split1(v1, h1, l1);
                __nv_bfloat162 hv, lv; hv.x = h0; hv.y = h1; lv.x = l0; lv.y = l1;
                *(__nv_bfloat162*)(Ch + (size_t)r0 * N + c0) = hv;
                *(__nv_bfloat162*)(Cl + (size_t)r0 * N + c0) = lv;
                split1(v2, h0, l0); split1(v3, h1, l1);
                hv.x = h0; hv.y = h1; lv.x = l0; lv.y = l1;
                *(__nv_bfloat162*)(Ch + (size_t)(r0 + 8) * N + c0) = hv;
                *(__nv_bfloat162*)(Cl + (size_t)(r0 + 8) * N + c0) = lv;
            } else if (epi == 0) {
                *(float2*)(C + (size_t)r0 * N + c0)       = make_float2(v0, v1);
                *(float2*)(C + (size_t)(r0 + 8) * N + c0) = make_float2(v2, v3);
            }
        }
    }
}

// ============================ pre-pass kernels ============================

// W [K,N] fp32 -> Wt hi/lo [N,K] bf16. 32x32 tiles, block (32,8).
__global__ void splitT_k(const float* __restrict__ W, bf16* __restrict__ ht,
                         bf16* __restrict__ lt, int K, int N)
{
    __shared__ float t[32][33];
    const int n0 = blockIdx.x * 32, k0 = blockIdx.y * 32;
    const int tx = threadIdx.x, ty = threadIdx.y;
    #pragma unroll
    for (int i = 0; i < 4; i++)
        t[ty + i * 8][tx] = W[(size_t)(k0 + ty + i * 8) * N + n0 + tx];
    __syncthreads();
    #pragma unroll
    for (int i = 0; i < 4; i++) {
        const int n = ty + i * 8;
        float v = t[tx][n];
        bf16 h, l; split1(v, h, l);
        const size_t o = (size_t)(n0 + n) * K + k0 + tx;
        ht[o] = h; lt[o] = l;
    }
}

__global__ void split_pair_k(const float* __restrict__ x, bf16* __restrict__ h,
                             bf16* __restrict__ l)
{
    const size_t i4 = ((size_t)blockIdx.x * 256 + threadIdx.x) * 4;
    float4 v = *(const float4*)(x + i4);
    bf16 h0,l0,h1,l1,h2,l2,h3,l3;
    split1(v.x,h0,l0); split1(v.y,h1,l1); split1(v.z,h2,l2); split1(v.w,h3,l3);
    __nv_bfloat162 a,b,c,d;
    a.x=h0;a.y=h1; b.x=h2;b.y=h3; c.x=l0;c.y=l1; d.x=l2;d.y=l3;
    *(__nv_bfloat162*)(h + i4)     = a; *(__nv_bfloat162*)(h + i4 + 2) = b;
    *(__nv_bfloat162*)(l + i4)     = c; *(__nv_bfloat162*)(l + i4 + 2) = d;
}

// ============================ elementwise / rowwise ============================

__device__ __forceinline__ void blockReduce2(float& a, float& b) {
    __shared__ float sb[16];
    #pragma unroll
    for (int o = 16; o > 0; o >>= 1) {
        a += __shfl_down_sync(0xffffffffu, a, o);
        b += __shfl_down_sync(0xffffffffu, b, o);
    }
    int lane = threadIdx.x & 31, w = threadIdx.x >> 5;
    __syncthreads();
    if (lane == 0) { sb[w] = a; sb[8 + w] = b; }
    __syncthreads();
    if (w == 0) {
        a = (lane < 8) ? sb[lane] : 0.0f;
        b = (lane < 8) ? sb[8 + lane] : 0.0f;
        #pragma unroll
        for (int o = 4; o > 0; o >>= 1) {
            a += __shfl_down_sync(0xffffffffu, a, o);
            b += __shfl_down_sync(0xffffffffu, b, o);
        }
        if (lane == 0) { sb[0] = a; sb[8] = b; }
    }
    __syncthreads();
    a = sb[0]; b = sb[8];
}

// kqb[n] = dot(qb, kW[n,:]) — one block per n
__global__ __launch_bounds__(256) void kqb_k(
    const float* __restrict__ kW, const float* __restrict__ qb)
{
    const int n = blockIdx.x;
    float s = 0.0f, dummy = 0.0f;
    for (int e = threadIdx.x; e < DIM; e += 256)
        s += qb[e] * kW[(size_t)n * DIM + e];
    blockReduce2(s, dummy);
    if (threadIdx.x == 0) g_kqb[n] = s;
}

__global__ __launch_bounds__(256) void ln_gelu_split_k(
    const float* __restrict__ X, const float* __restrict__ g, const float* __restrict__ b,
    int N, bf16* __restrict__ oh, bf16* __restrict__ ol)
{
    const float* x = X + (size_t)blockIdx.x * N;
    float s = 0.0f, q = 0.0f;
    for (int i = threadIdx.x; i < N; i += 256) { float t = x[i]; s += t; q += t * t; }
    blockReduce2(s, q);
    float mu = s / N;
    float rstd = rsqrtf(q / N - mu * mu + EPSV);
    for (int i = threadIdx.x; i < N; i += 256) {
        float t = gelu_exact((x[i] - mu) * rstd * g[i] + b[i]);
        bf16 h, l; split1(t, h, l);
        oh[(size_t)blockIdx.x * N + i] = h;
        ol[(size_t)blockIdx.x * N + i] = l;
    }
}

// per row: s1 = qk.f1, s2 = qk.f2 -> softmax2 -> vmix = w1 f1 + w2 f2 (split bf16)
__global__ __launch_bounds__(256) void score_vmix_k(
    const float* __restrict__ f1, const float* __restrict__ f2)
{
    const size_t base = (size_t)blockIdx.x * DIM;
    const int tid = threadIdx.x;
    float t1[8], t2[8];
    float s1 = 0.0f, s2 = 0.0f;
    #pragma unroll
    for (int j = 0; j < 8; j++) {
        int c = tid + j * 256;
        float qq = g_qk[base + c];
        t1[j] = f1[base + c]; t2[j] = f2[base + c];
        s1 += qq * t1[j];
        s2 += qq * t2[j];
    }
    blockReduce2(s1, s2);
    const float inv = rsqrtf((float)DIM);
    float w1 = 1.0f / (1.0f + expf((s2 - s1) * inv));
    float w2 = 1.0f - w1;
    #pragma unroll
    for (int j = 0; j < 8; j++) {
        int c = tid + j * 256;
        float v = w1 * t1[j] + w2 * t2[j];
        bf16 h, l; split1(v, h, l);
        g_vmh[base + c] = h; g_vml[base + c] = l;
    }
}

// t = gf + attn -> LN(aln) -> +f1 -> LN(ln1) -> r1
__global__ __launch_bounds__(256) void attn2_k(
    const float* __restrict__ f1,
    const float* __restrict__ alng, const float* __restrict__ alnb,
    const float* __restrict__ ln1g, const float* __restrict__ ln1b)
{
    const size_t base = (size_t)blockIdx.x * DIM;
    const int tid = threadIdx.x;
    float t[8]; float s = 0.0f, q = 0.0f;
    #pragma unroll
    for (int j = 0; j < 8; j++) {
        int c = tid + j * 256;
        float tv = g_gf[base + c] + g_attn[base + c];
        t[j] = tv; s += tv; q += tv * tv;
    }
    blockReduce2(s, q);
    float mu = s / DIM, rstd = rsqrtf(q / DIM - mu * mu + EPSV);

    float r[8]; s = 0.0f; q = 0.0f;
    #pragma unroll
    for (int j = 0; j < 8; j++) {
        int c = tid + j * 256;
        float gv = (t[j] - mu) * rstd * alng[c] + alnb[c];
        float rv = gv + f1[base + c];
        r[j] = rv; s += rv; q += rv * rv;
    }
    blockReduce2(s, q);
    mu = s / DIM; rstd = rsqrtf(q / DIM - mu * mu + EPSV);
    #pragma unroll
    for (int j = 0; j < 8; j++) {
        int c = tid + j * 256;
        g_r1[base + c] = (r[j] - mu) * rstd * ln1g[c] + ln1b[c];
    }
}

__global__ void zero_k() {
    int i = blockIdx.x * 256 + threadIdx.x;
    if (i < NASP * DIM) { g_sum[i] = 0.0f; g_sq[i] = 0.0f; }
    if (i < NASP) g_cnt[i] = 0.0f;
}

__global__ void cnt_k(const int* __restrict__ asp) {
    __shared__ int c[NASP];
    if (threadIdx.x < NASP) c[threadIdx.x] = 0;
    __syncthreads();
    for (int i = threadIdx.x; i < BSZ; i += blockDim.x) atomicAdd(&c[asp[i]], 1);
    __syncthreads();
    if (threadIdx.x < NASP) g_cnt[threadIdx.x] = (float)c[threadIdx.x];
}

__global__ __launch_bounds__(128) void bnstat_k(const int* __restrict__ asp) {
    int col = blockIdx.x * 128 + threadIdx.x;
    int r0 = blockIdx.y * 128;
    float m0 = 0, m1 = 0, m2 = 0, q0 = 0, q1 = 0, q2 = 0;
    for (int r = r0; r < r0 + 128; r++) {
        int a = asp[r];
        float x = g_r1[(size_t)r * DIM + col];
        float xx = x * x;
        if (a == 0)      { m0 += x; q0 += xx; }
        else if (a == 1) { m1 += x; q1 += xx; }
        else             { m2 += x; q2 += xx; }
    }
    atomicAdd(&g_sum[0 * DIM + col], m0); atomicAdd(&g_sq[0 * DIM + col], q0);
    atomicAdd(&g_sum[1 * DIM + col], m1); atomicAdd(&g_sq[1 * DIM + col], q1);
    atomicAdd(&g_sum[2 * DIM + col], m2); atomicAdd(&g_sq[2 * DIM + col], q2);
}

__global__ void bnfin_k(const float* __restrict__ bng, const float* __restrict__ bnb) {
    int i = blockIdx.x * 256 + threadIdx.x;
    if (i >= NASP * DIM) return;
    int a = i / DIM;
    float safe = fmaxf(g_cnt[a], 1.0f);
    float mean = g_sum[i] / safe;
    float var  = g_sq[i] / safe - mean * mean;
    float sc = rsqrtf(var + EPSV) * bng[i];
    g_scale[i] = sc;
    g_shift[i] = bnb[i] - mean * sc;
}

__global__ __launch_bounds__(256) void bnapply_split_k(const int* __restrict__ asp) {
    int row = blockIdx.x;
    int a = asp[row];
    bool norm = g_cnt[a] > 1.0f;
    size_t base = (size_t)row * DIM;
    for (int c = threadIdx.x; c < DIM; c += 256) {
        float x = g_r1[base + c];
        float o = norm ? fmaf(x, g_scale[a * DIM + c], g_shift[a * DIM + c]) : x;
        g_r1[base + c] = o;
        bf16 h, l; split1(o, h, l);
        g_r1h[base + c] = h; g_r1l[base + c] = l;
    }
}

__global__ __launch_bounds__(256) void final_k(
    float* __restrict__ out,
    const float* __restrict__ ln2g, const float* __restrict__ ln2b)
{
    const size_t base = (size_t)blockIdx.x * DIM;
    const int tid = threadIdx.x;
    float t[8]; float s = 0.0f, q = 0.0f;
    #pragma unroll
    for (int j = 0; j < 8; j++) {
        int c = tid + j * 256;
        float tv = g_ffn[base + c] + g_r1[base + c];
        t[j] = tv; s += tv; q += tv * tv;
    }
    blockReduce2(s, q);
    float mu = s / DIM, rstd = rsqrtf(q / DIM - mu * mu + EPSV);
    #pragma unroll
    for (int j = 0; j < 8; j++) {
        int c = tid + j * 256;
        out[base + c] = (t[j] - mu) * rstd * ln2g[c] + ln2b[c];
    }
}

// ============================ launch ============================
extern "C" void kernel_launch(void* const* d_in, const int* in_sizes, int n_in,
                              void* d_out, int out_size)
{
    (void)in_sizes; (void)n_in; (void)out_size;
    const float* f1   = (const float*)d_in[0];
    const float* f2   = (const float*)d_in[1];
    const int*   asp  = (const int*)  d_in[2];
    const float* gW1  = (const float*)d_in[3];
    const float* gb1  = (const float*)d_in[4];
    const float* gl1g = (const float*)d_in[5];
    const float* gl1b = (const float*)d_in[6];
    const float* gW2  = (const float*)d_in[7];
    const float* gb2  = (const float*)d_in[8];
    const float* gl2g = (const float*)d_in[9];
    const float* gl2b = (const float*)d_in[10];
    const float* gW3  = (const float*)d_in[11];
    const float* gb3  = (const float*)d_in[12];
    const float* qW   = (const float*)d_in[13];
    const float* qb   = (const float*)d_in[14];
    const float* kW   = (const float*)d_in[15];
    const float* vW   = (const float*)d_in[17];
    const float* vb   = (const float*)d_in[18];
    const float* alng = (const float*)d_in[19];
    const float* alnb = (const float*)d_in[20];
    const float* bng  = (const float*)d_in[21];
    const float* bnb  = (const float*)d_in[22];
    const float* ln1g = (const float*)d_in[23];
    const float* ln1b = (const float*)d_in[24];
    const float* fW1  = (const float*)d_in[25];
    const float* fb1  = (const float*)d_in[26];
    const float* fW2  = (const float*)d_in[27];
    const float* fb2  = (const float*)d_in[28];
    const float* ln2g = (const float*)d_in[29];
    const float* ln2b = (const float*)d_in[30];
    float* out = (float*)d_out;

    cudaFuncSetAttribute(gemm_mma_k, cudaFuncAttributeMaxDynamicSharedMemorySize, GEMM_SMEM_BYTES);

    float *p_h1, *p_h2, *p_gf, *p_qk, *p_attn, *p_r1, *p_ffn, *p_kqb;
    bf16 *p_f1h, *p_f1l, *p_f2h, *p_f2l, *p_h1h, *p_h1l, *p_h2h, *p_h2l;
    bf16 *p_gfh, *p_gfl, *p_vmh, *p_vml, *p_r1h, *p_r1l, *p_hidh, *p_hidl;
    bf16 *pw_g1h, *pw_g1l, *pw_g2h, *pw_g2l, *pw_g3h, *pw_g3l;
    bf16 *pw_kh, *pw_kl, *pw_qoh, *pw_qol, *pw_vh, *pw_vl, *pw_f1h, *pw_f1l, *pw_f2h, *pw_f2l;
    bf16 *p_mth, *p_mtl;
    cudaGetSymbolAddress((void**)&p_h1, g_h1);   cudaGetSymbolAddress((void**)&p_h2, g_h2);
    cudaGetSymbolAddress((void**)&p_gf, g_gf);   cudaGetSymbolAddress((void**)&p_qk, g_qk);
    cudaGetSymbolAddress((void**)&p_attn, g_attn);
    cudaGetSymbolAddress((void**)&p_r1, g_r1);   cudaGetSymbolAddress((void**)&p_ffn, g_ffn);
    cudaGetSymbolAddress((void**)&p_kqb, g_kqb);
    cudaGetSymbolAddress((void**)&p_f1h, g_f1h); cudaGetSymbolAddress((void**)&p_f1l, g_f1l);
    cudaGetSymbolAddress((void**)&p_f2h, g_f2h); cudaGetSymbolAddress((void**)&p_f2l, g_f2l);
    cudaGetSymbolAddress((void**)&p_h1h, g_h1h); cudaGetSymbolAddress((void**)&p_h1l, g_h1l);
    cudaGetSymbolAddress((void**)&p_h2h, g_h2h); cudaGetSymbolAddress((void**)&p_h2l, g_h2l);
    cudaGetSymbolAddress((void**)&p_gfh, g_gfh); cudaGetSymbolAddress((void**)&p_gfl, g_gfl);
    cudaGetSymbolAddress((void**)&p_vmh, g_vmh); cudaGetSymbolAddress((void**)&p_vml, g_vml);
    cudaGetSymbolAddress((void**)&p_r1h, g_r1h); cudaGetSymbolAddress((void**)&p_r1l, g_r1l);
    cudaGetSymbolAddress((void**)&p_hidh, g_hidh); cudaGetSymbolAddress((void**)&p_hidl, g_hidl);
    cudaGetSymbolAddress((void**)&pw_g1h, w_g1h); cudaGetSymbolAddress((void**)&pw_g1l, w_g1l);
    cudaGetSymbolAddress((void**)&pw_g2h, w_g2h); cudaGetSymbolAddress((void**)&pw_g2l, w_g2l);
    cudaGetSymbolAddress((void**)&pw_g3h, w_g3h); cudaGetSymbolAddress((void**)&pw_g3l, w_g3l);
    cudaGetSymbolAddress((void**)&pw_kh, w_kh);   cudaGetSymbolAddress((void**)&pw_kl, w_kl);
    cudaGetSymbolAddress((void**)&pw_qoh, w_qoh); cudaGetSymbolAddress((void**)&pw_qol, w_qol);
    cudaGetSymbolAddress((void**)&pw_vh, w_vh);   cudaGetSymbolAddress((void**)&pw_vl, w_vl);
    cudaGetSymbolAddress((void**)&pw_f1h, w_f1h); cudaGetSymbolAddress((void**)&pw_f1l, w_f1l);
    cudaGetSymbolAddress((void**)&pw_f2h, w_f2h); cudaGetSymbolAddress((void**)&pw_f2l, w_f2l);
    cudaGetSymbolAddress((void**)&p_mth, m_th);   cudaGetSymbolAddress((void**)&p_mtl, m_tl);

    dim3 tb(32, 8);
    splitT_k<<<dim3(HID/32, (2*DIM)/32), tb>>>(gW1, pw_g1h, pw_g1l, 2*DIM, HID);
    splitT_k<<<dim3((HID/2)/32, HID/32), tb>>>(gW2, pw_g2h, pw_g2l, HID, HID/2);
    splitT_k<<<dim3(DIM/32, (HID/2)/32), tb>>>(gW3, pw_g3h, pw_g3l, HID/2, DIM);
    splitT_k<<<dim3(DIM/32, DIM/32), tb>>>(vW, pw_vh, pw_vl, DIM, DIM);
    splitT_k<<<dim3((2*DIM)/32, DIM/32), tb>>>(fW1, pw_f1h, pw_f1l, DIM, 2*DIM);
    splitT_k<<<dim3(DIM/32, (2*DIM)/32), tb>>>(fW2, pw_f2h, pw_f2l, 2*DIM, DIM);
    split_pair_k<<<(DIM*DIM)/1024, 256>>>(kW, pw_kh, pw_kl);   // kW [D,D] as-is
    split_pair_k<<<(DIM*DIM)/1024, 256>>>(qW, pw_qoh, pw_qol); // qW [D,D] as-is
    kqb_k<<<DIM, 256>>>(kW, qb);

    split_pair_k<<<(BSZ*DIM)/1024, 256>>>(f1, p_f1h, p_f1l);
    split_pair_k<<<(BSZ*DIM)/1024, 256>>>(f2, p_f2h, p_f2l);

    #define GEMM(A_h, A_l, A2h, A2l, B_h, B_l, bias, Fa, Fb, Cf, Chh, Cll, Mv, Nv, Kv, Asv, Ksv, ep) \
        gemm_mma_k<<<dim3((Nv)/BN, (Mv)/BM), 256, GEMM_SMEM_BYTES>>>( \
            A_h, A_l, A2h, A2l, B_h, B_l, bias, Fa, Fb, Cf, Chh, Cll, Mv, Nv, Kv, Asv, Ksv, ep)

    // Mt = kW @ qW^T  (weight-space fold of q-projection into score projection)
    GEMM(pw_kh, pw_kl, nullptr, nullptr, pw_qoh, pw_qol, nullptr, nullptr, nullptr,
         nullptr, p_mth, p_mtl, DIM, DIM, DIM, DIM, 0, 4);

    // gate MLP (G1 reads [f1|f2] splits directly via concat-A mode)
    GEMM(p_f1h, p_f1l, p_f2h, p_f2l, pw_g1h, pw_g1l, gb1, nullptr, nullptr,
         p_h1, nullptr, nullptr, BSZ, HID, 2*DIM, DIM, DIM, 0);
    ln_gelu_split_k<<<BSZ, 256>>>(p_h1, gl1g, gl1b, HID, p_h1h, p_h1l);
    GEMM(p_h1h, p_h1l, nullptr, nullptr, pw_g2h, pw_g2l, gb2, nullptr, nullptr,
         p_h2, nullptr, nullptr, BSZ, HID/2, HID, HID, 0, 0);
    ln_gelu_split_k<<<BSZ, 256>>>(p_h2, gl2g, gl2b, HID/2, p_h2h, p_h2l);
    // G3: gate fused -> gf fp32 + split
    GEMM(p_h2h, p_h2l, nullptr, nullptr, pw_g3h, pw_g3l, gb3, f1, f2,
         p_gf, p_gfh, p_gfl, BSZ, DIM, HID/2, HID/2, 0, 3);

    // attention: qk = gf @ Mt^T + kqb  (q-projection folded) -> scores/vmix -> v-projection
    GEMM(p_gfh, p_gfl, nullptr, nullptr, p_mth, p_mtl, p_kqb, nullptr, nullptr,
         p_qk, nullptr, nullptr, BSZ, DIM, DIM, DIM, 0, 0);
    score_vmix_k<<<BSZ, 256>>>(f1, f2);
    GEMM(p_vmh, p_vml, nullptr, nullptr, pw_vh, pw_vl, vb, nullptr, nullptr,
         p_attn, nullptr, nullptr, BSZ, DIM, DIM, DIM, 0, 0);

    attn2_k<<<BSZ, 256>>>(f1, alng, alnb, ln1g, ln1b);

    // aspect BN
    zero_k<<<(NASP*DIM + 255)/256, 256>>>();
    cnt_k<<<1, 256>>>(asp);
    bnstat_k<<<dim3(DIM/128, BSZ/128), 128>>>(asp);
    bnfin_k<<<(NASP*DIM + 255)/256, 256>>>(bng, bnb);
    bnapply_split_k<<<BSZ, 256>>>(asp);

    // FFN
    GEMM(p_r1h, p_r1l, nullptr, nullptr, pw_f1h, pw_f1l, fb1, nullptr, nullptr,
         nullptr, p_hidh, p_hidl, BSZ, 2*DIM, DIM, DIM, 0, 2);
    GEMM(p_hidh, p_hidl, nullptr, nullptr, pw_f2h, pw_f2l, fb2, nullptr, nullptr,
         p_ffn, nullptr, nullptr, BSZ, DIM, 2*DIM, 2*DIM, 0, 0);

    final_k<<<BSZ, 256>>>(out, ln2g, ln2b);
}